// round 12
// baseline (speedup 1.0000x reference)
#include <cuda_runtime.h>
#include <cuda_fp16.h>
#include <cstdint>

typedef unsigned long long ULL;

__device__ __forceinline__ uint32_t smem_u32(const void* p){
    uint32_t a;
    asm("{ .reg .u64 t; cvta.to.shared.u64 t, %1; cvt.u32.u64 %0, t; }" : "=r"(a) : "l"(p));
    return a;
}
__device__ __forceinline__ ULL f2dup(float x) {
    ULL r; asm("mov.b64 %0, {%1,%1};" : "=l"(r) : "f"(x)); return r;
}
__device__ __forceinline__ float2 f2unpack(ULL v) {
    float2 r; asm("mov.b64 {%0,%1}, %2;" : "=f"(r.x), "=f"(r.y) : "l"(v)); return r;
}
__device__ __forceinline__ ULL ffma2(ULL a, ULL b, ULL c) {
    ULL d; asm("fma.rn.f32x2 %0, %1, %2, %3;" : "=l"(d) : "l"(a), "l"(b), "l"(c)); return d;
}

#define LDSM4(rg, addr) \
    asm volatile("ldmatrix.sync.aligned.m8n8.x4.shared.b16 {%0,%1,%2,%3}, [%4];" \
        : "=r"((rg)[0]), "=r"((rg)[1]), "=r"((rg)[2]), "=r"((rg)[3]) : "r"(addr))

__device__ __forceinline__ void mma_f16(float* c, const uint32_t* a, uint32_t b0, uint32_t b1){
    asm volatile("mma.sync.aligned.m16n8k16.row.col.f32.f16.f16.f32 "
        "{%0,%1,%2,%3}, {%4,%5,%6,%7}, {%8,%9}, {%0,%1,%2,%3};"
        : "+f"(c[0]), "+f"(c[1]), "+f"(c[2]), "+f"(c[3])
        : "r"(a[0]), "r"(a[1]), "r"(a[2]), "r"(a[3]), "r"(b0), "r"(b1));
}

#define TAU 1.5e-2f

__device__ __half g_Bhi[2][65536];
__device__ __half g_Blo[2][65536];
__device__ int g_cnt;
__device__ int g_list[131072];

__global__ void prep_kernel(const float* __restrict__ W1, const float* __restrict__ W2){
    if (blockIdx.x == 0 && threadIdx.x == 0) g_cnt = 0;
    int i = blockIdx.x * 256 + threadIdx.x;   // 0..65535
    int k = i >> 8, n = i & 255;
    int dst = (k >> 5) * 8192 + ((n >> 3) * 4 + ((k >> 3) & 3)) * 64 + (n & 7) * 8 + (k & 7);
    {
        float v = W1[k * 256 + n];
        __half hi = __float2half_rn(v);
        g_Bhi[0][dst] = hi;
        g_Blo[0][dst] = __float2half_rn(v - __half2float(hi));
    }
    {
        float v = W2[k * 256 + n];
        __half hi = __float2half_rn(v);
        g_Bhi[1][dst] = hi;
        g_Blo[1][dst] = __float2half_rn(v - __half2float(hi));
    }
}

// ---- exact fp32 fixup v3: 32 rows/block, thread j = column j ----
// smem: xa [256][36] + xb [256][36] + lgs [32][24]
#define FR 32
#define XPAD 36
#define FIX_SMEM ((2 * 256 * XPAD + FR * 24) * 4)
__global__ void __launch_bounds__(256) fixup_kernel(
    const float* __restrict__ X,
    const float* __restrict__ W1, const float* __restrict__ b1,
    const float* __restrict__ W2, const float* __restrict__ b2,
    const float* __restrict__ W3, const float* __restrict__ b3,
    float* __restrict__ out)
{
    extern __shared__ float fsm[];
    float* xa  = fsm;                       // [k][XPAD]
    float* xb  = fsm + 256 * XPAD;          // [k][XPAD]
    float* lgs = fsm + 2 * 256 * XPAD;      // [r][24]
    __shared__ int rows[FR];
    const int j = threadIdx.x;
    const int n = g_cnt;

    for (int base = blockIdx.x * FR; base < n; base += gridDim.x * FR) {
        const int nb = min(FR, n - base);
        if (j < FR) rows[j] = g_list[base + min(j, nb - 1)];
        __syncthreads();
        // gather X: thread j reads col j of each row -> xa[j][r]
        #pragma unroll 4
        for (int r = 0; r < FR; ++r)
            xa[j * XPAD + r] = X[(size_t)rows[r] * 256 + j];
        __syncthreads();
        // layer 1: 32 independent k-sequential fp32 chains per thread
        {
            float s[FR];
            #pragma unroll
            for (int r = 0; r < FR; ++r) s[r] = 0.0f;
            #pragma unroll 2
            for (int k = 0; k < 256; ++k) {
                float wv = W1[(size_t)k * 256 + j];
                #pragma unroll
                for (int q = 0; q < 8; ++q) {
                    float4 av = *(const float4*)(xa + k * XPAD + q * 4);
                    s[4*q]   = fmaf(av.x, wv, s[4*q]);
                    s[4*q+1] = fmaf(av.y, wv, s[4*q+1]);
                    s[4*q+2] = fmaf(av.z, wv, s[4*q+2]);
                    s[4*q+3] = fmaf(av.w, wv, s[4*q+3]);
                }
            }
            float bb = b1[j];
            #pragma unroll
            for (int r = 0; r < FR; ++r) xb[j * XPAD + r] = fmaxf(s[r] + bb, 0.0f);
        }
        __syncthreads();
        // layer 2
        {
            float s[FR];
            #pragma unroll
            for (int r = 0; r < FR; ++r) s[r] = 0.0f;
            #pragma unroll 2
            for (int k = 0; k < 256; ++k) {
                float wv = W2[(size_t)k * 256 + j];
                #pragma unroll
                for (int q = 0; q < 8; ++q) {
                    float4 av = *(const float4*)(xb + k * XPAD + q * 4);
                    s[4*q]   = fmaf(av.x, wv, s[4*q]);
                    s[4*q+1] = fmaf(av.y, wv, s[4*q+1]);
                    s[4*q+2] = fmaf(av.z, wv, s[4*q+2]);
                    s[4*q+3] = fmaf(av.w, wv, s[4*q+3]);
                }
            }
            float bb = b2[j];
            #pragma unroll
            for (int r = 0; r < FR; ++r) xa[j * XPAD + r] = fmaxf(s[r] + bb, 0.0f);
        }
        __syncthreads();
        // layer 3 (24 columns)
        if (j < 24) {
            float s[FR];
            #pragma unroll
            for (int r = 0; r < FR; ++r) s[r] = 0.0f;
            #pragma unroll 2
            for (int k = 0; k < 256; ++k) {
                float wv = W3[(size_t)k * 24 + j];
                #pragma unroll
                for (int q = 0; q < 8; ++q) {
                    float4 av = *(const float4*)(xa + k * XPAD + q * 4);
                    s[4*q]   = fmaf(av.x, wv, s[4*q]);
                    s[4*q+1] = fmaf(av.y, wv, s[4*q+1]);
                    s[4*q+2] = fmaf(av.z, wv, s[4*q+2]);
                    s[4*q+3] = fmaf(av.w, wv, s[4*q+3]);
                }
            }
            float bb = b3[j];
            #pragma unroll
            for (int r = 0; r < FR; ++r) lgs[r * 24 + j] = s[r] + bb;
        }
        __syncthreads();
        // top-6: thread r handles row r
        if (j < nb) {
            float v[24];
            #pragma unroll
            for (int c = 0; c < 24; ++c) v[c] = lgs[j * 24 + c];
            unsigned chosen = 1u | (1u << 12);
            #pragma unroll
            for (int it = 0; it < 6; ++it) {
                float best = -3.402823466e38f;
                int bi = 1;
                #pragma unroll
                for (int c = 1; c < 24; ++c) {
                    if (c == 12) continue;
                    bool free_ = !((chosen >> c) & 1u);
                    if (free_ && v[c] > best) { best = v[c]; bi = c; }
                }
                chosen |= (1u << bi);
            }
            float* op = out + (size_t)rows[j] * 24;
            #pragma unroll
            for (int c = 0; c < 24; ++c) op[c] = ((chosen >> c) & 1u) ? 1.0f : 0.0f;
        }
        __syncthreads();
    }
}

// smem (bytes):
//   Ahi [128r x 256k] f16 tiled @ 0 (65536)
//   B 2 bufs x (hi 16K + lo 16K) @ 65536 (65536)
//   overlays after layer 2 (B dead): W3s @ 65536 (24576), logit_s @ 90112 (12800)
#define OFF_AHI 0
#define OFF_B   65536
#define B_STRIDE 32768
#define OFF_W3  65536
#define OFF_LG  90112
#define SMEM_BYTES 131072

__global__ void __launch_bounds__(256, 1) fused_mlp_hmma(
    const float* __restrict__ X,
    const float* __restrict__ b1, const float* __restrict__ b2,
    const float* __restrict__ W3, const float* __restrict__ b3,
    float* __restrict__ out)
{
    extern __shared__ char smc[];
    __half* Ahi = (__half*)(smc + OFF_AHI);

    const int tid  = threadIdx.x;
    const int w    = tid >> 5;
    const int lane = tid & 31;
    const int bm0  = blockIdx.x * 128;
    const uint32_t smb = smem_u32(smc);

    const int rg = w >> 1;
    const int cg = w & 1;

    // ---- X -> A hi tiles (fp16 round only; residual dropped, fixup covers) ----
    #pragma unroll
    for (int u = 0; u < 32; ++u) {
        int i = tid + u * 256;
        int row = i >> 6, kq = (i & 63) * 4;
        float4 v = *(const float4*)(X + (size_t)(bm0 + row) * 256 + kq);
        int off = ((row >> 3) * 32 + (kq >> 3)) * 64 + (row & 7) * 8 + (kq & 7);
        *(__half2*)(Ahi + off)     = __halves2half2(__float2half_rn(v.x), __float2half_rn(v.y));
        *(__half2*)(Ahi + off + 2) = __halves2half2(__float2half_rn(v.z), __float2half_rn(v.w));
    }
    {
        const float4* shi = (const float4*)(g_Bhi[0]);
        const float4* slo = (const float4*)(g_Blo[0]);
        float4* dhi = (float4*)(smc + OFF_B);
        float4* dlo = (float4*)(smc + OFF_B + 16384);
        #pragma unroll
        for (int u = 0; u < 4; ++u) { int i = tid + u * 256; dhi[i] = shi[i]; dlo[i] = slo[i]; }
    }
    __syncthreads();

    const int m = lane >> 3, r = lane & 7;
    const uint32_t aTail0 = (uint32_t)(((rg * 4 + 0 + (m & 1)) * 32 + (m >> 1)) * 128 + r * 16);
    const uint32_t aTail1 = (uint32_t)(((rg * 4 + 2 + (m & 1)) * 32 + (m >> 1)) * 128 + r * 16);
    const uint32_t aHi0 = smb + OFF_AHI + aTail0;
    const uint32_t aHi1 = smb + OFF_AHI + aTail1;
    const uint32_t bBase = (uint32_t)(((m >> 1) * 4 + (m & 1)) * 128 + r * 16);

    const int g   = lane >> 2;
    const int tig = lane & 3;

    float acc[2][16][4];

    #pragma unroll 1
    for (int l = 0; l < 2; ++l) {
        #pragma unroll
        for (int t = 0; t < 2; ++t)
            #pragma unroll
            for (int nt = 0; nt < 16; ++nt)
                #pragma unroll
                for (int q = 0; q < 4; ++q) acc[t][nt][q] = 0.0f;

        #pragma unroll 1
        for (int kc = 0; kc < 8; ++kc) {
            const int c   = l * 8 + kc;
            const int buf = c & 1;
            if (c < 15) {
                const int cn = c + 1;
                const float4* shi = (const float4*)(g_Bhi[cn >> 3] + (cn & 7) * 8192);
                const float4* slo = (const float4*)(g_Blo[cn >> 3] + (cn & 7) * 8192);
                float4* dhi = (float4*)(smc + OFF_B + (buf ^ 1) * B_STRIDE);
                float4* dlo = (float4*)(smc + OFF_B + (buf ^ 1) * B_STRIDE + 16384);
                #pragma unroll
                for (int u = 0; u < 4; ++u) { int i = tid + u * 256; dhi[i] = shi[i]; dlo[i] = slo[i]; }
            }
            const uint32_t bhB = smb + OFF_B + buf * B_STRIDE + bBase + cg * 8192;
            const uint32_t blB = bhB + 16384;
            #pragma unroll
            for (int ks = 0; ks < 2; ++ks) {
                const uint32_t koff = (uint32_t)((kc * 2 + ks) * 256);
                uint32_t ah[2][4];
                LDSM4(ah[0], aHi0 + koff);
                LDSM4(ah[1], aHi1 + koff);
                #pragma unroll
                for (int nt2 = 0; nt2 < 8; ++nt2) {
                    uint32_t bh[4], bl[4];
                    LDSM4(bh, bhB + nt2 * 1024 + ks * 256);
                    LDSM4(bl, blB + nt2 * 1024 + ks * 256);
                    #pragma unroll
                    for (int t = 0; t < 2; ++t) {
                        mma_f16(acc[t][2 * nt2],     ah[t], bh[0], bh[1]);
                        mma_f16(acc[t][2 * nt2],     ah[t], bl[0], bl[1]);
                        mma_f16(acc[t][2 * nt2 + 1], ah[t], bh[2], bh[3]);
                        mma_f16(acc[t][2 * nt2 + 1], ah[t], bl[2], bl[3]);
                    }
                }
            }
            __syncthreads();
        }

        // ---- epilogue: bias + relu -> A hi (in place) ----
        const float* bias = l ? b2 : b1;
        #pragma unroll
        for (int t = 0; t < 2; ++t) {
            const int r0 = rg * 32 + t * 16 + g;
            const int r1 = r0 + 8;
            #pragma unroll
            for (int nt = 0; nt < 16; ++nt) {
                int c0 = cg * 128 + nt * 8 + 2 * tig;
                float2 bb = __ldg((const float2*)(bias + c0));
                float v0 = fmaxf(acc[t][nt][0] + bb.x, 0.0f);
                float v1 = fmaxf(acc[t][nt][1] + bb.y, 0.0f);
                float v2 = fmaxf(acc[t][nt][2] + bb.x, 0.0f);
                float v3 = fmaxf(acc[t][nt][3] + bb.y, 0.0f);
                int off0 = ((r0 >> 3) * 32 + (c0 >> 3)) * 64 + (r0 & 7) * 8 + (c0 & 7);
                int off1 = ((r1 >> 3) * 32 + (c0 >> 3)) * 64 + (r1 & 7) * 8 + (c0 & 7);
                *(__half2*)(Ahi + off0) = __halves2half2(__float2half_rn(v0), __float2half_rn(v1));
                *(__half2*)(Ahi + off1) = __halves2half2(__float2half_rn(v2), __float2half_rn(v3));
            }
        }
        __syncthreads();
    }

    // ---- stage W3 (fp32) into dead B region ----
    {
        float* W3s = (float*)(smc + OFF_W3);
        #pragma unroll
        for (int u = 0; u < 6; ++u) {
            int i = tid + u * 256;
            ((float4*)W3s)[i] = ((const float4*)W3)[i];
        }
    }
    __syncthreads();

    // ---- Layer 3: logits = h @ W3 + b3 (FFMA2, h = hi) ----
    {
        float* logit_s = (float*)(smc + OFF_LG);
        const ULL* W3s64 = (const ULL*)(smc + OFF_W3);
        const int rp = tid & 63;
        const int gq = tid >> 6;
        const int ra = rp, rb = rp + 64;
        const int baseA = (ra >> 3) * 2048 + (ra & 7) * 8;
        const int baseB = (rb >> 3) * 2048 + (rb & 7) * 8;
        ULL a3[2][3];
        #pragma unroll
        for (int j = 0; j < 3; ++j) { a3[0][j] = 0ULL; a3[1][j] = 0ULL; }
        #pragma unroll 4
        for (int kt = 0; kt < 32; ++kt) {
            uint4 h0 = *(const uint4*)(Ahi + baseA + kt * 64);
            uint4 h1 = *(const uint4*)(Ahi + baseB + kt * 64);
            float x0[8], x1[8];
            const __half2* hp0 = (const __half2*)&h0;
            const __half2* hp1 = (const __half2*)&h1;
            #pragma unroll
            for (int q = 0; q < 4; ++q) {
                float2 a = __half22float2(hp0[q]);
                x0[2*q] = a.x; x0[2*q+1] = a.y;
                float2 cpp = __half22float2(hp1[q]);
                x1[2*q] = cpp.x; x1[2*q+1] = cpp.y;
            }
            #pragma unroll
            for (int kk = 0; kk < 8; ++kk) {
                int k = kt * 8 + kk;
                ULL a0 = f2dup(x0[kk]);
                ULL a1 = f2dup(x1[kk]);
                #pragma unroll
                for (int j = 0; j < 3; ++j) {
                    ULL wv = W3s64[k * 12 + 3 * gq + j];
                    a3[0][j] = ffma2(a0, wv, a3[0][j]);
                    a3[1][j] = ffma2(a1, wv, a3[1][j]);
                }
            }
        }
        #pragma unroll
        for (int j = 0; j < 3; ++j) {
            float2 bb = ((const float2*)b3)[3 * gq + j];
            float2 v0 = f2unpack(a3[0][j]);
            float2 v1 = f2unpack(a3[1][j]);
            logit_s[ra * 25 + 6 * gq + 2 * j]     = v0.x + bb.x;
            logit_s[ra * 25 + 6 * gq + 2 * j + 1] = v0.y + bb.y;
            logit_s[rb * 25 + 6 * gq + 2 * j]     = v1.x + bb.x;
            logit_s[rb * 25 + 6 * gq + 2 * j + 1] = v1.y + bb.y;
        }
    }
    __syncthreads();

    // ---- top-6 of 22 selected + borderline flagging + write ----
    if (tid < 128) {
        const float* logit_s = (const float*)(smc + OFF_LG);
        const int row = bm0 + tid;
        float v[24];
        #pragma unroll
        for (int c = 0; c < 24; ++c) v[c] = logit_s[tid * 25 + c];

        unsigned chosen = 1u | (1u << 12);
        float lastBest = 0.0f;
        #pragma unroll
        for (int it = 0; it < 6; ++it) {
            float best = -3.402823466e38f;
            int bi = 1;
            #pragma unroll
            for (int c = 1; c < 24; ++c) {
                if (c == 12) continue;
                bool free_ = !((chosen >> c) & 1u);
                if (free_ && v[c] > best) { best = v[c]; bi = c; }  // strict >: lower index wins ties
            }
            chosen |= (1u << bi);
            lastBest = best;
        }
        float v7 = -3.402823466e38f;
        #pragma unroll
        for (int c = 1; c < 24; ++c) {
            if (c == 12) continue;
            if (!((chosen >> c) & 1u)) v7 = fmaxf(v7, v[c]);
        }
        if (lastBest - v7 < TAU) {
            int idx = atomicAdd(&g_cnt, 1);
            g_list[idx] = row;
        }

        float o[24];
        #pragma unroll
        for (int c = 0; c < 24; ++c) o[c] = ((chosen >> c) & 1u) ? 1.0f : 0.0f;
        float4* op = (float4*)(out + (size_t)row * 24);
        #pragma unroll
        for (int g2 = 0; g2 < 6; ++g2)
            op[g2] = make_float4(o[4 * g2], o[4 * g2 + 1], o[4 * g2 + 2], o[4 * g2 + 3]);
    }
}

extern "C" void kernel_launch(void* const* d_in, const int* in_sizes, int n_in,
                              void* d_out, int out_size) {
    const float* X  = (const float*)d_in[0];
    const float* W1 = (const float*)d_in[1];
    const float* b1 = (const float*)d_in[2];
    const float* W2 = (const float*)d_in[3];
    const float* b2 = (const float*)d_in[4];
    const float* W3 = (const float*)d_in[5];
    const float* b3 = (const float*)d_in[6];
    float* out = (float*)d_out;

    int B = in_sizes[0] / 256;

    prep_kernel<<<256, 256>>>(W1, W2);

    cudaFuncSetAttribute(fused_mlp_hmma, cudaFuncAttributeMaxDynamicSharedMemorySize, SMEM_BYTES);
    fused_mlp_hmma<<<B / 128, 256, SMEM_BYTES>>>(X, b1, b2, W3, b3, out);

    cudaFuncSetAttribute(fixup_kernel, cudaFuncAttributeMaxDynamicSharedMemorySize, FIX_SMEM);
    fixup_kernel<<<1024, 256, FIX_SMEM>>>(X, W1, b1, W2, b2, W3, b3, out);
}

// round 13
// speedup vs baseline: 1.2095x; 1.2095x over previous
#include <cuda_runtime.h>
#include <cuda_fp16.h>
#include <cstdint>

typedef unsigned long long ULL;

__device__ __forceinline__ uint32_t smem_u32(const void* p){
    uint32_t a;
    asm("{ .reg .u64 t; cvta.to.shared.u64 t, %1; cvt.u32.u64 %0, t; }" : "=r"(a) : "l"(p));
    return a;
}
__device__ __forceinline__ ULL f2dup(float x) {
    ULL r; asm("mov.b64 %0, {%1,%1};" : "=l"(r) : "f"(x)); return r;
}
__device__ __forceinline__ float2 f2unpack(ULL v) {
    float2 r; asm("mov.b64 {%0,%1}, %2;" : "=f"(r.x), "=f"(r.y) : "l"(v)); return r;
}
__device__ __forceinline__ ULL ffma2(ULL a, ULL b, ULL c) {
    ULL d; asm("fma.rn.f32x2 %0, %1, %2, %3;" : "=l"(d) : "l"(a), "l"(b), "l"(c)); return d;
}

#define LDSM4(rg, addr) \
    asm volatile("ldmatrix.sync.aligned.m8n8.x4.shared.b16 {%0,%1,%2,%3}, [%4];" \
        : "=r"((rg)[0]), "=r"((rg)[1]), "=r"((rg)[2]), "=r"((rg)[3]) : "r"(addr))

__device__ __forceinline__ void mma_f16(float* c, const uint32_t* a, uint32_t b0, uint32_t b1){
    asm volatile("mma.sync.aligned.m16n8k16.row.col.f32.f16.f16.f32 "
        "{%0,%1,%2,%3}, {%4,%5,%6,%7}, {%8,%9}, {%0,%1,%2,%3};"
        : "+f"(c[0]), "+f"(c[1]), "+f"(c[2]), "+f"(c[3])
        : "r"(a[0]), "r"(a[1]), "r"(a[2]), "r"(a[3]), "r"(b0), "r"(b1));
}

#define TAU 1.5e-4f

__device__ __half g_Bhi[2][65536];
__device__ __half g_Blo[2][65536];
__device__ int g_cnt;
__device__ int g_list[131072];

__global__ void prep_kernel(const float* __restrict__ W1, const float* __restrict__ W2){
    if (blockIdx.x == 0 && threadIdx.x == 0) g_cnt = 0;
    int i = blockIdx.x * 256 + threadIdx.x;   // 0..65535
    int k = i >> 8, n = i & 255;
    int dst = (k >> 5) * 8192 + ((n >> 3) * 4 + ((k >> 3) & 3)) * 64 + (n & 7) * 8 + (k & 7);
    {
        float v = W1[k * 256 + n];
        __half hi = __float2half_rn(v);
        g_Bhi[0][dst] = hi;
        g_Blo[0][dst] = __float2half_rn(v - __half2float(hi));
    }
    {
        float v = W2[k * 256 + n];
        __half hi = __float2half_rn(v);
        g_Bhi[1][dst] = hi;
        g_Blo[1][dst] = __float2half_rn(v - __half2float(hi));
    }
}

// ---- exact fp32 fixup v3: 32 rows/block, thread j = column j ----
#define FR 32
#define XPAD 36
#define FIX_SMEM ((2 * 256 * XPAD + FR * 24) * 4)
__global__ void __launch_bounds__(256) fixup_kernel(
    const float* __restrict__ X,
    const float* __restrict__ W1, const float* __restrict__ b1,
    const float* __restrict__ W2, const float* __restrict__ b2,
    const float* __restrict__ W3, const float* __restrict__ b3,
    float* __restrict__ out)
{
    extern __shared__ float fsm[];
    float* xa  = fsm;                       // [k][XPAD]
    float* xb  = fsm + 256 * XPAD;          // [k][XPAD]
    float* lgs = fsm + 2 * 256 * XPAD;      // [r][24]
    __shared__ int rows[FR];
    const int j = threadIdx.x;
    const int n = g_cnt;

    for (int base = blockIdx.x * FR; base < n; base += gridDim.x * FR) {
        const int nb = min(FR, n - base);
        if (j < FR) rows[j] = g_list[base + min(j, nb - 1)];
        __syncthreads();
        #pragma unroll 4
        for (int r = 0; r < FR; ++r)
            xa[j * XPAD + r] = X[(size_t)rows[r] * 256 + j];
        __syncthreads();
        // layer 1
        {
            float s[FR];
            #pragma unroll
            for (int r = 0; r < FR; ++r) s[r] = 0.0f;
            #pragma unroll 2
            for (int k = 0; k < 256; ++k) {
                float wv = W1[(size_t)k * 256 + j];
                #pragma unroll
                for (int q = 0; q < 8; ++q) {
                    float4 av = *(const float4*)(xa + k * XPAD + q * 4);
                    s[4*q]   = fmaf(av.x, wv, s[4*q]);
                    s[4*q+1] = fmaf(av.y, wv, s[4*q+1]);
                    s[4*q+2] = fmaf(av.z, wv, s[4*q+2]);
                    s[4*q+3] = fmaf(av.w, wv, s[4*q+3]);
                }
            }
            float bb = b1[j];
            #pragma unroll
            for (int r = 0; r < FR; ++r) xb[j * XPAD + r] = fmaxf(s[r] + bb, 0.0f);
        }
        __syncthreads();
        // layer 2
        {
            float s[FR];
            #pragma unroll
            for (int r = 0; r < FR; ++r) s[r] = 0.0f;
            #pragma unroll 2
            for (int k = 0; k < 256; ++k) {
                float wv = W2[(size_t)k * 256 + j];
                #pragma unroll
                for (int q = 0; q < 8; ++q) {
                    float4 av = *(const float4*)(xb + k * XPAD + q * 4);
                    s[4*q]   = fmaf(av.x, wv, s[4*q]);
                    s[4*q+1] = fmaf(av.y, wv, s[4*q+1]);
                    s[4*q+2] = fmaf(av.z, wv, s[4*q+2]);
                    s[4*q+3] = fmaf(av.w, wv, s[4*q+3]);
                }
            }
            float bb = b2[j];
            #pragma unroll
            for (int r = 0; r < FR; ++r) xa[j * XPAD + r] = fmaxf(s[r] + bb, 0.0f);
        }
        __syncthreads();
        // layer 3
        if (j < 24) {
            float s[FR];
            #pragma unroll
            for (int r = 0; r < FR; ++r) s[r] = 0.0f;
            #pragma unroll 2
            for (int k = 0; k < 256; ++k) {
                float wv = W3[(size_t)k * 24 + j];
                #pragma unroll
                for (int q = 0; q < 8; ++q) {
                    float4 av = *(const float4*)(xa + k * XPAD + q * 4);
                    s[4*q]   = fmaf(av.x, wv, s[4*q]);
                    s[4*q+1] = fmaf(av.y, wv, s[4*q+1]);
                    s[4*q+2] = fmaf(av.z, wv, s[4*q+2]);
                    s[4*q+3] = fmaf(av.w, wv, s[4*q+3]);
                }
            }
            float bb = b3[j];
            #pragma unroll
            for (int r = 0; r < FR; ++r) lgs[r * 24 + j] = s[r] + bb;
        }
        __syncthreads();
        if (j < nb) {
            float v[24];
            #pragma unroll
            for (int c = 0; c < 24; ++c) v[c] = lgs[j * 24 + c];
            unsigned chosen = 1u | (1u << 12);
            #pragma unroll
            for (int it = 0; it < 6; ++it) {
                float best = -3.402823466e38f;
                int bi = 1;
                #pragma unroll
                for (int c = 1; c < 24; ++c) {
                    if (c == 12) continue;
                    bool free_ = !((chosen >> c) & 1u);
                    if (free_ && v[c] > best) { best = v[c]; bi = c; }
                }
                chosen |= (1u << bi);
            }
            float* op = out + (size_t)rows[j] * 24;
            #pragma unroll
            for (int c = 0; c < 24; ++c) op[c] = ((chosen >> c) & 1u) ? 1.0f : 0.0f;
        }
        __syncthreads();
    }
}

// smem (bytes):
//   Ahi [128r x 256k] f16 tiled @ 0 (65536); Alo @ 65536 (65536)
//   B 2 bufs x (hi 16K + lo 16K) @ 131072 (65536)
//   overlays after layer 2: W3s @ 131072 (24576), logit_s @ 155648 (12800)
#define OFF_AHI 0
#define OFF_ALO 65536
#define OFF_B   131072
#define B_STRIDE 32768
#define OFF_W3  131072
#define OFF_LG  155648
#define SMEM_BYTES 196608

__global__ void __launch_bounds__(256, 1) fused_mlp_hmma(
    const float* __restrict__ X,
    const float* __restrict__ b1, const float* __restrict__ b2,
    const float* __restrict__ W3, const float* __restrict__ b3,
    float* __restrict__ out)
{
    extern __shared__ char smc[];
    __half* Ahi = (__half*)(smc + OFF_AHI);
    __half* Alo = (__half*)(smc + OFF_ALO);

    const int tid  = threadIdx.x;
    const int w    = tid >> 5;
    const int lane = tid & 31;
    const int bm0  = blockIdx.x * 128;
    const uint32_t smb = smem_u32(smc);

    const int rg = w >> 1;
    const int cg = w & 1;

    // ---- X -> A hi/lo tiles ----
    #pragma unroll
    for (int u = 0; u < 32; ++u) {
        int i = tid + u * 256;
        int row = i >> 6, kq = (i & 63) * 4;
        float4 v = *(const float4*)(X + (size_t)(bm0 + row) * 256 + kq);
        int off = ((row >> 3) * 32 + (kq >> 3)) * 64 + (row & 7) * 8 + (kq & 7);
        __half hx = __float2half_rn(v.x), hy = __float2half_rn(v.y);
        __half hz = __float2half_rn(v.z), hw = __float2half_rn(v.w);
        *(__half2*)(Ahi + off)     = __halves2half2(hx, hy);
        *(__half2*)(Ahi + off + 2) = __halves2half2(hz, hw);
        *(__half2*)(Alo + off)     = __halves2half2(__float2half_rn(v.x - __half2float(hx)),
                                                    __float2half_rn(v.y - __half2float(hy)));
        *(__half2*)(Alo + off + 2) = __halves2half2(__float2half_rn(v.z - __half2float(hz)),
                                                    __float2half_rn(v.w - __half2float(hw)));
    }
    {
        const float4* shi = (const float4*)(g_Bhi[0]);
        const float4* slo = (const float4*)(g_Blo[0]);
        float4* dhi = (float4*)(smc + OFF_B);
        float4* dlo = (float4*)(smc + OFF_B + 16384);
        #pragma unroll
        for (int u = 0; u < 4; ++u) { int i = tid + u * 256; dhi[i] = shi[i]; dlo[i] = slo[i]; }
    }
    __syncthreads();

    const int m = lane >> 3, r = lane & 7;
    const uint32_t aTail0 = (uint32_t)(((rg * 4 + 0 + (m & 1)) * 32 + (m >> 1)) * 128 + r * 16);
    const uint32_t aTail1 = (uint32_t)(((rg * 4 + 2 + (m & 1)) * 32 + (m >> 1)) * 128 + r * 16);
    const uint32_t aHi0 = smb + OFF_AHI + aTail0;
    const uint32_t aHi1 = smb + OFF_AHI + aTail1;
    const uint32_t aLo0 = smb + OFF_ALO + aTail0;
    const uint32_t aLo1 = smb + OFF_ALO + aTail1;
    const uint32_t bBase = (uint32_t)(((m >> 1) * 4 + (m & 1)) * 128 + r * 16);

    const int g   = lane >> 2;
    const int tig = lane & 3;

    float acc[2][16][4];

    #pragma unroll 1
    for (int l = 0; l < 2; ++l) {
        #pragma unroll
        for (int t = 0; t < 2; ++t)
            #pragma unroll
            for (int nt = 0; nt < 16; ++nt)
                #pragma unroll
                for (int q = 0; q < 4; ++q) acc[t][nt][q] = 0.0f;

        #pragma unroll 1
        for (int kc = 0; kc < 8; ++kc) {
            const int c   = l * 8 + kc;
            const int buf = c & 1;
            if (c < 15) {
                const int cn = c + 1;
                const float4* shi = (const float4*)(g_Bhi[cn >> 3] + (cn & 7) * 8192);
                const float4* slo = (const float4*)(g_Blo[cn >> 3] + (cn & 7) * 8192);
                float4* dhi = (float4*)(smc + OFF_B + (buf ^ 1) * B_STRIDE);
                float4* dlo = (float4*)(smc + OFF_B + (buf ^ 1) * B_STRIDE + 16384);
                #pragma unroll
                for (int u = 0; u < 4; ++u) { int i = tid + u * 256; dhi[i] = shi[i]; dlo[i] = slo[i]; }
            }
            const uint32_t bhB = smb + OFF_B + buf * B_STRIDE + bBase + cg * 8192;
            const uint32_t blB = bhB + 16384;
            #pragma unroll
            for (int ks = 0; ks < 2; ++ks) {
                const uint32_t koff = (uint32_t)((kc * 2 + ks) * 256);
                uint32_t ah[2][4], al[2][4];
                LDSM4(ah[0], aHi0 + koff);
                LDSM4(ah[1], aHi1 + koff);
                LDSM4(al[0], aLo0 + koff);
                LDSM4(al[1], aLo1 + koff);
                #pragma unroll
                for (int nt2 = 0; nt2 < 8; ++nt2) {
                    uint32_t bh[4], bl[4];
                    LDSM4(bh, bhB + nt2 * 1024 + ks * 256);
                    LDSM4(bl, blB + nt2 * 1024 + ks * 256);
                    #pragma unroll
                    for (int t = 0; t < 2; ++t) {
                        mma_f16(acc[t][2 * nt2],     ah[t], bh[0], bh[1]);
                        mma_f16(acc[t][2 * nt2],     ah[t], bl[0], bl[1]);
                        mma_f16(acc[t][2 * nt2],     al[t], bh[0], bh[1]);
                        mma_f16(acc[t][2 * nt2 + 1], ah[t], bh[2], bh[3]);
                        mma_f16(acc[t][2 * nt2 + 1], ah[t], bl[2], bl[3]);
                        mma_f16(acc[t][2 * nt2 + 1], al[t], bh[2], bh[3]);
                    }
                }
            }
            __syncthreads();
        }

        // ---- epilogue: bias + relu + fp16 split -> A (in place) ----
        const float* bias = l ? b2 : b1;
        #pragma unroll
        for (int t = 0; t < 2; ++t) {
            const int r0 = rg * 32 + t * 16 + g;
            const int r1 = r0 + 8;
            #pragma unroll
            for (int nt = 0; nt < 16; ++nt) {
                int c0 = cg * 128 + nt * 8 + 2 * tig;
                float2 bb = __ldg((const float2*)(bias + c0));
                float v0 = fmaxf(acc[t][nt][0] + bb.x, 0.0f);
                float v1 = fmaxf(acc[t][nt][1] + bb.y, 0.0f);
                float v2 = fmaxf(acc[t][nt][2] + bb.x, 0.0f);
                float v3 = fmaxf(acc[t][nt][3] + bb.y, 0.0f);
                int off0 = ((r0 >> 3) * 32 + (c0 >> 3)) * 64 + (r0 & 7) * 8 + (c0 & 7);
                int off1 = ((r1 >> 3) * 32 + (c0 >> 3)) * 64 + (r1 & 7) * 8 + (c0 & 7);
                __half h0 = __float2half_rn(v0), h1 = __float2half_rn(v1);
                __half h2 = __float2half_rn(v2), h3 = __float2half_rn(v3);
                *(__half2*)(Ahi + off0) = __halves2half2(h0, h1);
                *(__half2*)(Ahi + off1) = __halves2half2(h2, h3);
                *(__half2*)(Alo + off0) = __halves2half2(__float2half_rn(v0 - __half2float(h0)),
                                                         __float2half_rn(v1 - __half2float(h1)));
                *(__half2*)(Alo + off1) = __halves2half2(__float2half_rn(v2 - __half2float(h2)),
                                                         __float2half_rn(v3 - __half2float(h3)));
            }
        }
        __syncthreads();
    }

    // ---- stage W3 (fp32) into dead B region ----
    {
        float* W3s = (float*)(smc + OFF_W3);
        #pragma unroll
        for (int u = 0; u < 6; ++u) {
            int i = tid + u * 256;
            ((float4*)W3s)[i] = ((const float4*)W3)[i];
        }
    }
    __syncthreads();

    // ---- Layer 3: logits = h @ W3 + b3 (FFMA2, h = hi+lo) ----
    {
        float* logit_s = (float*)(smc + OFF_LG);
        const ULL* W3s64 = (const ULL*)(smc + OFF_W3);
        const int rp = tid & 63;
        const int gq = tid >> 6;
        const int ra = rp, rb = rp + 64;
        const int baseA = (ra >> 3) * 2048 + (ra & 7) * 8;
        const int baseB = (rb >> 3) * 2048 + (rb & 7) * 8;
        ULL a3[2][3];
        #pragma unroll
        for (int j = 0; j < 3; ++j) { a3[0][j] = 0ULL; a3[1][j] = 0ULL; }
        #pragma unroll 4
        for (int kt = 0; kt < 32; ++kt) {
            uint4 h0 = *(const uint4*)(Ahi + baseA + kt * 64);
            uint4 l0 = *(const uint4*)(Alo + baseA + kt * 64);
            uint4 h1 = *(const uint4*)(Ahi + baseB + kt * 64);
            uint4 l1 = *(const uint4*)(Alo + baseB + kt * 64);
            float x0[8], x1[8];
            const __half2* hp0 = (const __half2*)&h0;
            const __half2* lp0 = (const __half2*)&l0;
            const __half2* hp1 = (const __half2*)&h1;
            const __half2* lp1 = (const __half2*)&l1;
            #pragma unroll
            for (int q = 0; q < 4; ++q) {
                float2 a = __half22float2(hp0[q]), b = __half22float2(lp0[q]);
                x0[2*q] = a.x + b.x; x0[2*q+1] = a.y + b.y;
                float2 cpp = __half22float2(hp1[q]), d = __half22float2(lp1[q]);
                x1[2*q] = cpp.x + d.x; x1[2*q+1] = cpp.y + d.y;
            }
            #pragma unroll
            for (int kk = 0; kk < 8; ++kk) {
                int k = kt * 8 + kk;
                ULL a0 = f2dup(x0[kk]);
                ULL a1 = f2dup(x1[kk]);
                #pragma unroll
                for (int j = 0; j < 3; ++j) {
                    ULL wv = W3s64[k * 12 + 3 * gq + j];
                    a3[0][j] = ffma2(a0, wv, a3[0][j]);
                    a3[1][j] = ffma2(a1, wv, a3[1][j]);
                }
            }
        }
        #pragma unroll
        for (int j = 0; j < 3; ++j) {
            float2 bb = ((const float2*)b3)[3 * gq + j];
            float2 v0 = f2unpack(a3[0][j]);
            float2 v1 = f2unpack(a3[1][j]);
            logit_s[ra * 25 + 6 * gq + 2 * j]     = v0.x + bb.x;
            logit_s[ra * 25 + 6 * gq + 2 * j + 1] = v0.y + bb.y;
            logit_s[rb * 25 + 6 * gq + 2 * j]     = v1.x + bb.x;
            logit_s[rb * 25 + 6 * gq + 2 * j + 1] = v1.y + bb.y;
        }
    }
    __syncthreads();

    // ---- top-6 of 22 selected + borderline flagging + write ----
    if (tid < 128) {
        const float* logit_s = (const float*)(smc + OFF_LG);
        const int row = bm0 + tid;
        float v[24];
        #pragma unroll
        for (int c = 0; c < 24; ++c) v[c] = logit_s[tid * 25 + c];

        unsigned chosen = 1u | (1u << 12);
        float lastBest = 0.0f;
        #pragma unroll
        for (int it = 0; it < 6; ++it) {
            float best = -3.402823466e38f;
            int bi = 1;
            #pragma unroll
            for (int c = 1; c < 24; ++c) {
                if (c == 12) continue;
                bool free_ = !((chosen >> c) & 1u);
                if (free_ && v[c] > best) { best = v[c]; bi = c; }  // strict >: lower index wins ties
            }
            chosen |= (1u << bi);
            lastBest = best;
        }
        float v7 = -3.402823466e38f;
        #pragma unroll
        for (int c = 1; c < 24; ++c) {
            if (c == 12) continue;
            if (!((chosen >> c) & 1u)) v7 = fmaxf(v7, v[c]);
        }
        if (lastBest - v7 < TAU) {
            int idx = atomicAdd(&g_cnt, 1);
            g_list[idx] = row;
        }

        float o[24];
        #pragma unroll
        for (int c = 0; c < 24; ++c) o[c] = ((chosen >> c) & 1u) ? 1.0f : 0.0f;
        float4* op = (float4*)(out + (size_t)row * 24);
        #pragma unroll
        for (int g2 = 0; g2 < 6; ++g2)
            op[g2] = make_float4(o[4 * g2], o[4 * g2 + 1], o[4 * g2 + 2], o[4 * g2 + 3]);
    }
}

extern "C" void kernel_launch(void* const* d_in, const int* in_sizes, int n_in,
                              void* d_out, int out_size) {
    const float* X  = (const float*)d_in[0];
    const float* W1 = (const float*)d_in[1];
    const float* b1 = (const float*)d_in[2];
    const float* W2 = (const float*)d_in[3];
    const float* b2 = (const float*)d_in[4];
    const float* W3 = (const float*)d_in[5];
    const float* b3 = (const float*)d_in[6];
    float* out = (float*)d_out;

    int B = in_sizes[0] / 256;

    prep_kernel<<<256, 256>>>(W1, W2);

    cudaFuncSetAttribute(fused_mlp_hmma, cudaFuncAttributeMaxDynamicSharedMemorySize, SMEM_BYTES);
    fused_mlp_hmma<<<B / 128, 256, SMEM_BYTES>>>(X, b1, b2, W3, b3, out);

    cudaFuncSetAttribute(fixup_kernel, cudaFuncAttributeMaxDynamicSharedMemorySize, FIX_SMEM);
    fixup_kernel<<<128, 256, FIX_SMEM>>>(X, W1, b1, W2, b2, W3, b3, out);
}

// round 14
// speedup vs baseline: 1.5909x; 1.3153x over previous
#include <cuda_runtime.h>
#include <cuda_fp16.h>
#include <cstdint>

typedef unsigned long long ULL;

__device__ __forceinline__ uint32_t smem_u32(const void* p){
    uint32_t a;
    asm("{ .reg .u64 t; cvta.to.shared.u64 t, %1; cvt.u32.u64 %0, t; }" : "=r"(a) : "l"(p));
    return a;
}
__device__ __forceinline__ ULL f2dup(float x) {
    ULL r; asm("mov.b64 %0, {%1,%1};" : "=l"(r) : "f"(x)); return r;
}
__device__ __forceinline__ float2 f2unpack(ULL v) {
    float2 r; asm("mov.b64 {%0,%1}, %2;" : "=f"(r.x), "=f"(r.y) : "l"(v)); return r;
}
__device__ __forceinline__ ULL ffma2(ULL a, ULL b, ULL c) {
    ULL d; asm("fma.rn.f32x2 %0, %1, %2, %3;" : "=l"(d) : "l"(a), "l"(b), "l"(c)); return d;
}

#define LDSM4(rg, addr) \
    asm volatile("ldmatrix.sync.aligned.m8n8.x4.shared.b16 {%0,%1,%2,%3}, [%4];" \
        : "=r"((rg)[0]), "=r"((rg)[1]), "=r"((rg)[2]), "=r"((rg)[3]) : "r"(addr))

__device__ __forceinline__ void mma_f16(float* c, const uint32_t* a, uint32_t b0, uint32_t b1){
    asm volatile("mma.sync.aligned.m16n8k16.row.col.f32.f16.f16.f32 "
        "{%0,%1,%2,%3}, {%4,%5,%6,%7}, {%8,%9}, {%0,%1,%2,%3};"
        : "+f"(c[0]), "+f"(c[1]), "+f"(c[2]), "+f"(c[3])
        : "r"(a[0]), "r"(a[1]), "r"(a[2]), "r"(a[3]), "r"(b0), "r"(b1));
}

#define TAU 3e-5f

__device__ __half g_Bhi[2][65536];
__device__ __half g_Blo[2][65536];
__device__ int g_cnt;
__device__ int g_list[131072];

__global__ void prep_kernel(const float* __restrict__ W1, const float* __restrict__ W2){
    if (blockIdx.x == 0 && threadIdx.x == 0) g_cnt = 0;
    int i = blockIdx.x * 256 + threadIdx.x;   // 0..65535
    int k = i >> 8, n = i & 255;
    int dst = (k >> 5) * 8192 + ((n >> 3) * 4 + ((k >> 3) & 3)) * 64 + (n & 7) * 8 + (k & 7);
    {
        float v = W1[k * 256 + n];
        __half hi = __float2half_rn(v);
        g_Bhi[0][dst] = hi;
        g_Blo[0][dst] = __float2half_rn(v - __half2float(hi));
    }
    {
        float v = W2[k * 256 + n];
        __half hi = __float2half_rn(v);
        g_Bhi[1][dst] = hi;
        g_Blo[1][dst] = __float2half_rn(v - __half2float(hi));
    }
}

// ---- exact fp32 fixup: ONE ROW PER BLOCK, thread j owns column j ----
__global__ void __launch_bounds__(256) fixup_kernel(
    const float* __restrict__ X,
    const float* __restrict__ W1, const float* __restrict__ b1,
    const float* __restrict__ W2, const float* __restrict__ b2,
    const float* __restrict__ W3, const float* __restrict__ b3,
    float* __restrict__ out)
{
    __shared__ float xa[256];
    __shared__ float xb[256];
    __shared__ float lgs[24];
    const int j = threadIdx.x;
    const int n = g_cnt;

    for (int i = blockIdx.x; i < n; i += gridDim.x) {
        const int row = g_list[i];
        xa[j] = X[(size_t)row * 256 + j];
        __syncthreads();
        // layer 1 (thread j = output col j), k-sequential fp32 FMA
        {
            float s = 0.0f;
            #pragma unroll 8
            for (int k = 0; k < 256; ++k) s = fmaf(xa[k], W1[(size_t)k * 256 + j], s);
            xb[j] = fmaxf(s + b1[j], 0.0f);
        }
        __syncthreads();
        // layer 2
        {
            float s = 0.0f;
            #pragma unroll 8
            for (int k = 0; k < 256; ++k) s = fmaf(xb[k], W2[(size_t)k * 256 + j], s);
            xa[j] = fmaxf(s + b2[j], 0.0f);
        }
        __syncthreads();
        // layer 3
        if (j < 24) {
            float s = 0.0f;
            #pragma unroll 8
            for (int k = 0; k < 256; ++k) s = fmaf(xa[k], W3[(size_t)k * 24 + j], s);
            lgs[j] = s + b3[j];
        }
        __syncthreads();
        if (j == 0) {
            float v[24];
            #pragma unroll
            for (int c = 0; c < 24; ++c) v[c] = lgs[c];
            unsigned chosen = 1u | (1u << 12);
            #pragma unroll
            for (int it = 0; it < 6; ++it) {
                float best = -3.402823466e38f;
                int bi = 1;
                #pragma unroll
                for (int c = 1; c < 24; ++c) {
                    if (c == 12) continue;
                    bool free_ = !((chosen >> c) & 1u);
                    if (free_ && v[c] > best) { best = v[c]; bi = c; }
                }
                chosen |= (1u << bi);
            }
            float* op = out + (size_t)row * 24;
            #pragma unroll
            for (int c = 0; c < 24; ++c) op[c] = ((chosen >> c) & 1u) ? 1.0f : 0.0f;
        }
        __syncthreads();
    }
}

// smem (bytes):
//   Ahi [128r x 256k] f16 tiled @ 0 (65536); Alo @ 65536 (65536)
//   B 2 bufs x (hi 16K + lo 16K) @ 131072 (65536)
//   overlays after layer 2: W3s @ 131072 (24576), logit_s @ 155648 (12800)
#define OFF_AHI 0
#define OFF_ALO 65536
#define OFF_B   131072
#define B_STRIDE 32768
#define OFF_W3  131072
#define OFF_LG  155648
#define SMEM_BYTES 196608

__global__ void __launch_bounds__(256, 1) fused_mlp_hmma(
    const float* __restrict__ X,
    const float* __restrict__ b1, const float* __restrict__ b2,
    const float* __restrict__ W3, const float* __restrict__ b3,
    float* __restrict__ out)
{
    extern __shared__ char smc[];
    __half* Ahi = (__half*)(smc + OFF_AHI);
    __half* Alo = (__half*)(smc + OFF_ALO);

    const int tid  = threadIdx.x;
    const int w    = tid >> 5;
    const int lane = tid & 31;
    const int bm0  = blockIdx.x * 128;
    const uint32_t smb = smem_u32(smc);

    const int rg = w >> 1;
    const int cg = w & 1;

    // ---- X -> A hi/lo tiles ----
    #pragma unroll
    for (int u = 0; u < 32; ++u) {
        int i = tid + u * 256;
        int row = i >> 6, kq = (i & 63) * 4;
        float4 v = *(const float4*)(X + (size_t)(bm0 + row) * 256 + kq);
        int off = ((row >> 3) * 32 + (kq >> 3)) * 64 + (row & 7) * 8 + (kq & 7);
        __half hx = __float2half_rn(v.x), hy = __float2half_rn(v.y);
        __half hz = __float2half_rn(v.z), hw = __float2half_rn(v.w);
        *(__half2*)(Ahi + off)     = __halves2half2(hx, hy);
        *(__half2*)(Ahi + off + 2) = __halves2half2(hz, hw);
        *(__half2*)(Alo + off)     = __halves2half2(__float2half_rn(v.x - __half2float(hx)),
                                                    __float2half_rn(v.y - __half2float(hy)));
        *(__half2*)(Alo + off + 2) = __halves2half2(__float2half_rn(v.z - __half2float(hz)),
                                                    __float2half_rn(v.w - __half2float(hw)));
    }
    {
        const float4* shi = (const float4*)(g_Bhi[0]);
        const float4* slo = (const float4*)(g_Blo[0]);
        float4* dhi = (float4*)(smc + OFF_B);
        float4* dlo = (float4*)(smc + OFF_B + 16384);
        #pragma unroll
        for (int u = 0; u < 4; ++u) { int i = tid + u * 256; dhi[i] = shi[i]; dlo[i] = slo[i]; }
    }
    __syncthreads();

    const int m = lane >> 3, r = lane & 7;
    const uint32_t aTail0 = (uint32_t)(((rg * 4 + 0 + (m & 1)) * 32 + (m >> 1)) * 128 + r * 16);
    const uint32_t aTail1 = (uint32_t)(((rg * 4 + 2 + (m & 1)) * 32 + (m >> 1)) * 128 + r * 16);
    const uint32_t aHi0 = smb + OFF_AHI + aTail0;
    const uint32_t aHi1 = smb + OFF_AHI + aTail1;
    const uint32_t aLo0 = smb + OFF_ALO + aTail0;
    const uint32_t aLo1 = smb + OFF_ALO + aTail1;
    const uint32_t bBase = (uint32_t)(((m >> 1) * 4 + (m & 1)) * 128 + r * 16);

    const int g   = lane >> 2;
    const int tig = lane & 3;

    float acc[2][16][4];

    #pragma unroll 1
    for (int l = 0; l < 2; ++l) {
        #pragma unroll
        for (int t = 0; t < 2; ++t)
            #pragma unroll
            for (int nt = 0; nt < 16; ++nt)
                #pragma unroll
                for (int q = 0; q < 4; ++q) acc[t][nt][q] = 0.0f;

        #pragma unroll 1
        for (int kc = 0; kc < 8; ++kc) {
            const int c   = l * 8 + kc;
            const int buf = c & 1;
            if (c < 15) {
                const int cn = c + 1;
                const float4* shi = (const float4*)(g_Bhi[cn >> 3] + (cn & 7) * 8192);
                const float4* slo = (const float4*)(g_Blo[cn >> 3] + (cn & 7) * 8192);
                float4* dhi = (float4*)(smc + OFF_B + (buf ^ 1) * B_STRIDE);
                float4* dlo = (float4*)(smc + OFF_B + (buf ^ 1) * B_STRIDE + 16384);
                #pragma unroll
                for (int u = 0; u < 4; ++u) { int i = tid + u * 256; dhi[i] = shi[i]; dlo[i] = slo[i]; }
            }
            const uint32_t bhB = smb + OFF_B + buf * B_STRIDE + bBase + cg * 8192;
            const uint32_t blB = bhB + 16384;
            #pragma unroll
            for (int ks = 0; ks < 2; ++ks) {
                const uint32_t koff = (uint32_t)((kc * 2 + ks) * 256);
                uint32_t ah[2][4], al[2][4];
                LDSM4(ah[0], aHi0 + koff);
                LDSM4(ah[1], aHi1 + koff);
                LDSM4(al[0], aLo0 + koff);
                LDSM4(al[1], aLo1 + koff);
                #pragma unroll
                for (int nt2 = 0; nt2 < 8; ++nt2) {
                    uint32_t bh[4], bl[4];
                    LDSM4(bh, bhB + nt2 * 1024 + ks * 256);
                    LDSM4(bl, blB + nt2 * 1024 + ks * 256);
                    #pragma unroll
                    for (int t = 0; t < 2; ++t) {
                        mma_f16(acc[t][2 * nt2],     ah[t], bh[0], bh[1]);
                        mma_f16(acc[t][2 * nt2],     ah[t], bl[0], bl[1]);
                        mma_f16(acc[t][2 * nt2],     al[t], bh[0], bh[1]);
                        mma_f16(acc[t][2 * nt2 + 1], ah[t], bh[2], bh[3]);
                        mma_f16(acc[t][2 * nt2 + 1], ah[t], bl[2], bl[3]);
                        mma_f16(acc[t][2 * nt2 + 1], al[t], bh[2], bh[3]);
                    }
                }
            }
            __syncthreads();
        }

        // ---- epilogue: bias + relu + fp16 split -> A (in place) ----
        const float* bias = l ? b2 : b1;
        #pragma unroll
        for (int t = 0; t < 2; ++t) {
            const int r0 = rg * 32 + t * 16 + g;
            const int r1 = r0 + 8;
            #pragma unroll
            for (int nt = 0; nt < 16; ++nt) {
                int c0 = cg * 128 + nt * 8 + 2 * tig;
                float2 bb = __ldg((const float2*)(bias + c0));
                float v0 = fmaxf(acc[t][nt][0] + bb.x, 0.0f);
                float v1 = fmaxf(acc[t][nt][1] + bb.y, 0.0f);
                float v2 = fmaxf(acc[t][nt][2] + bb.x, 0.0f);
                float v3 = fmaxf(acc[t][nt][3] + bb.y, 0.0f);
                int off0 = ((r0 >> 3) * 32 + (c0 >> 3)) * 64 + (r0 & 7) * 8 + (c0 & 7);
                int off1 = ((r1 >> 3) * 32 + (c0 >> 3)) * 64 + (r1 & 7) * 8 + (c0 & 7);
                __half h0 = __float2half_rn(v0), h1 = __float2half_rn(v1);
                __half h2 = __float2half_rn(v2), h3 = __float2half_rn(v3);
                *(__half2*)(Ahi + off0) = __halves2half2(h0, h1);
                *(__half2*)(Ahi + off1) = __halves2half2(h2, h3);
                *(__half2*)(Alo + off0) = __halves2half2(__float2half_rn(v0 - __half2float(h0)),
                                                         __float2half_rn(v1 - __half2float(h1)));
                *(__half2*)(Alo + off1) = __halves2half2(__float2half_rn(v2 - __half2float(h2)),
                                                         __float2half_rn(v3 - __half2float(h3)));
            }
        }
        __syncthreads();
    }

    // ---- stage W3 (fp32) into dead B region ----
    {
        float* W3s = (float*)(smc + OFF_W3);
        #pragma unroll
        for (int u = 0; u < 6; ++u) {
            int i = tid + u * 256;
            ((float4*)W3s)[i] = ((const float4*)W3)[i];
        }
    }
    __syncthreads();

    // ---- Layer 3: logits = h @ W3 + b3 (FFMA2, h = hi+lo) ----
    {
        float* logit_s = (float*)(smc + OFF_LG);
        const ULL* W3s64 = (const ULL*)(smc + OFF_W3);
        const int rp = tid & 63;
        const int gq = tid >> 6;
        const int ra = rp, rb = rp + 64;
        const int baseA = (ra >> 3) * 2048 + (ra & 7) * 8;
        const int baseB = (rb >> 3) * 2048 + (rb & 7) * 8;
        ULL a3[2][3];
        #pragma unroll
        for (int j = 0; j < 3; ++j) { a3[0][j] = 0ULL; a3[1][j] = 0ULL; }
        #pragma unroll 4
        for (int kt = 0; kt < 32; ++kt) {
            uint4 h0 = *(const uint4*)(Ahi + baseA + kt * 64);
            uint4 l0 = *(const uint4*)(Alo + baseA + kt * 64);
            uint4 h1 = *(const uint4*)(Ahi + baseB + kt * 64);
            uint4 l1 = *(const uint4*)(Alo + baseB + kt * 64);
            float x0[8], x1[8];
            const __half2* hp0 = (const __half2*)&h0;
            const __half2* lp0 = (const __half2*)&l0;
            const __half2* hp1 = (const __half2*)&h1;
            const __half2* lp1 = (const __half2*)&l1;
            #pragma unroll
            for (int q = 0; q < 4; ++q) {
                float2 a = __half22float2(hp0[q]), b = __half22float2(lp0[q]);
                x0[2*q] = a.x + b.x; x0[2*q+1] = a.y + b.y;
                float2 cpp = __half22float2(hp1[q]), d = __half22float2(lp1[q]);
                x1[2*q] = cpp.x + d.x; x1[2*q+1] = cpp.y + d.y;
            }
            #pragma unroll
            for (int kk = 0; kk < 8; ++kk) {
                int k = kt * 8 + kk;
                ULL a0 = f2dup(x0[kk]);
                ULL a1 = f2dup(x1[kk]);
                #pragma unroll
                for (int j = 0; j < 3; ++j) {
                    ULL wv = W3s64[k * 12 + 3 * gq + j];
                    a3[0][j] = ffma2(a0, wv, a3[0][j]);
                    a3[1][j] = ffma2(a1, wv, a3[1][j]);
                }
            }
        }
        #pragma unroll
        for (int j = 0; j < 3; ++j) {
            float2 bb = ((const float2*)b3)[3 * gq + j];
            float2 v0 = f2unpack(a3[0][j]);
            float2 v1 = f2unpack(a3[1][j]);
            logit_s[ra * 25 + 6 * gq + 2 * j]     = v0.x + bb.x;
            logit_s[ra * 25 + 6 * gq + 2 * j + 1] = v0.y + bb.y;
            logit_s[rb * 25 + 6 * gq + 2 * j]     = v1.x + bb.x;
            logit_s[rb * 25 + 6 * gq + 2 * j + 1] = v1.y + bb.y;
        }
    }
    __syncthreads();

    // ---- top-6 of 22 selected + borderline flagging + write ----
    if (tid < 128) {
        const float* logit_s = (const float*)(smc + OFF_LG);
        const int row = bm0 + tid;
        float v[24];
        #pragma unroll
        for (int c = 0; c < 24; ++c) v[c] = logit_s[tid * 25 + c];

        unsigned chosen = 1u | (1u << 12);
        float lastBest = 0.0f;
        #pragma unroll
        for (int it = 0; it < 6; ++it) {
            float best = -3.402823466e38f;
            int bi = 1;
            #pragma unroll
            for (int c = 1; c < 24; ++c) {
                if (c == 12) continue;
                bool free_ = !((chosen >> c) & 1u);
                if (free_ && v[c] > best) { best = v[c]; bi = c; }  // strict >: lower index wins ties
            }
            chosen |= (1u << bi);
            lastBest = best;
        }
        float v7 = -3.402823466e38f;
        #pragma unroll
        for (int c = 1; c < 24; ++c) {
            if (c == 12) continue;
            if (!((chosen >> c) & 1u)) v7 = fmaxf(v7, v[c]);
        }
        if (lastBest - v7 < TAU) {
            int idx = atomicAdd(&g_cnt, 1);
            g_list[idx] = row;
        }

        float o[24];
        #pragma unroll
        for (int c = 0; c < 24; ++c) o[c] = ((chosen >> c) & 1u) ? 1.0f : 0.0f;
        float4* op = (float4*)(out + (size_t)row * 24);
        #pragma unroll
        for (int g2 = 0; g2 < 6; ++g2)
            op[g2] = make_float4(o[4 * g2], o[4 * g2 + 1], o[4 * g2 + 2], o[4 * g2 + 3]);
    }
}

extern "C" void kernel_launch(void* const* d_in, const int* in_sizes, int n_in,
                              void* d_out, int out_size) {
    const float* X  = (const float*)d_in[0];
    const float* W1 = (const float*)d_in[1];
    const float* b1 = (const float*)d_in[2];
    const float* W2 = (const float*)d_in[3];
    const float* b2 = (const float*)d_in[4];
    const float* W3 = (const float*)d_in[5];
    const float* b3 = (const float*)d_in[6];
    float* out = (float*)d_out;

    int B = in_sizes[0] / 256;

    prep_kernel<<<256, 256>>>(W1, W2);

    cudaFuncSetAttribute(fused_mlp_hmma, cudaFuncAttributeMaxDynamicSharedMemorySize, SMEM_BYTES);
    fused_mlp_hmma<<<B / 128, 256, SMEM_BYTES>>>(X, b1, b2, W3, b3, out);

    fixup_kernel<<<1480, 256>>>(X, W1, b1, W2, b2, W3, b3, out);
}

// round 15
// speedup vs baseline: 1.6666x; 1.0476x over previous
#include <cuda_runtime.h>
#include <cuda_fp16.h>
#include <cstdint>

typedef unsigned long long ULL;

__device__ __forceinline__ uint32_t smem_u32(const void* p){
    uint32_t a;
    asm("{ .reg .u64 t; cvta.to.shared.u64 t, %1; cvt.u32.u64 %0, t; }" : "=r"(a) : "l"(p));
    return a;
}
__device__ __forceinline__ ULL f2dup(float x) {
    ULL r; asm("mov.b64 %0, {%1,%1};" : "=l"(r) : "f"(x)); return r;
}
__device__ __forceinline__ float2 f2unpack(ULL v) {
    float2 r; asm("mov.b64 {%0,%1}, %2;" : "=f"(r.x), "=f"(r.y) : "l"(v)); return r;
}
__device__ __forceinline__ ULL ffma2(ULL a, ULL b, ULL c) {
    ULL d; asm("fma.rn.f32x2 %0, %1, %2, %3;" : "=l"(d) : "l"(a), "l"(b), "l"(c)); return d;
}

#define LDSM4(rg, addr) \
    asm volatile("ldmatrix.sync.aligned.m8n8.x4.shared.b16 {%0,%1,%2,%3}, [%4];" \
        : "=r"((rg)[0]), "=r"((rg)[1]), "=r"((rg)[2]), "=r"((rg)[3]) : "r"(addr))

__device__ __forceinline__ void mma_f16(float* c, const uint32_t* a, uint32_t b0, uint32_t b1){
    asm volatile("mma.sync.aligned.m16n8k16.row.col.f32.f16.f16.f32 "
        "{%0,%1,%2,%3}, {%4,%5,%6,%7}, {%8,%9}, {%0,%1,%2,%3};"
        : "+f"(c[0]), "+f"(c[1]), "+f"(c[2]), "+f"(c[3])
        : "r"(a[0]), "r"(a[1]), "r"(a[2]), "r"(a[3]), "r"(b0), "r"(b1));
}

#define TAU 3e-5f

__device__ __half g_Bhi[2][65536];
__device__ __half g_Blo[2][65536];
__device__ int g_cnt;
__device__ int g_list[131072];

__global__ void prep_kernel(const float* __restrict__ W1, const float* __restrict__ W2){
    if (blockIdx.x == 0 && threadIdx.x == 0) g_cnt = 0;
    int i = blockIdx.x * 256 + threadIdx.x;   // 0..65535
    int k = i >> 8, n = i & 255;
    int dst = (k >> 5) * 8192 + ((n >> 3) * 4 + ((k >> 3) & 3)) * 64 + (n & 7) * 8 + (k & 7);
    {
        float v = W1[k * 256 + n];
        __half hi = __float2half_rn(v);
        g_Bhi[0][dst] = hi;
        g_Blo[0][dst] = __float2half_rn(v - __half2float(hi));
    }
    {
        float v = W2[k * 256 + n];
        __half hi = __float2half_rn(v);
        g_Bhi[1][dst] = hi;
        g_Blo[1][dst] = __float2half_rn(v - __half2float(hi));
    }
}

// ---- exact fp32 fixup: ONE ROW PER BLOCK, thread j owns column j ----
// unroll 32 => ~32 W loads in flight; load pipeline overlaps the serial FMA chain.
// Accumulation order identical to prior validated version (k-sequential).
__global__ void __launch_bounds__(256) fixup_kernel(
    const float* __restrict__ X,
    const float* __restrict__ W1, const float* __restrict__ b1,
    const float* __restrict__ W2, const float* __restrict__ b2,
    const float* __restrict__ W3, const float* __restrict__ b3,
    float* __restrict__ out)
{
    __shared__ float xa[256];
    __shared__ float xb[256];
    __shared__ float lgs[24];
    const int j = threadIdx.x;
    const int n = g_cnt;

    for (int i = blockIdx.x; i < n; i += gridDim.x) {
        const int row = g_list[i];
        xa[j] = X[(size_t)row * 256 + j];
        __syncthreads();
        // layer 1 (thread j = output col j), k-sequential fp32 FMA
        {
            float s = 0.0f;
            #pragma unroll 32
            for (int k = 0; k < 256; ++k) s = fmaf(xa[k], W1[(size_t)k * 256 + j], s);
            xb[j] = fmaxf(s + b1[j], 0.0f);
        }
        __syncthreads();
        // layer 2
        {
            float s = 0.0f;
            #pragma unroll 32
            for (int k = 0; k < 256; ++k) s = fmaf(xb[k], W2[(size_t)k * 256 + j], s);
            xa[j] = fmaxf(s + b2[j], 0.0f);
        }
        __syncthreads();
        // layer 3
        if (j < 24) {
            float s = 0.0f;
            #pragma unroll 32
            for (int k = 0; k < 256; ++k) s = fmaf(xa[k], W3[(size_t)k * 24 + j], s);
            lgs[j] = s + b3[j];
        }
        __syncthreads();
        if (j == 0) {
            float v[24];
            #pragma unroll
            for (int c = 0; c < 24; ++c) v[c] = lgs[c];
            unsigned chosen = 1u | (1u << 12);
            #pragma unroll
            for (int it = 0; it < 6; ++it) {
                float best = -3.402823466e38f;
                int bi = 1;
                #pragma unroll
                for (int c = 1; c < 24; ++c) {
                    if (c == 12) continue;
                    bool free_ = !((chosen >> c) & 1u);
                    if (free_ && v[c] > best) { best = v[c]; bi = c; }
                }
                chosen |= (1u << bi);
            }
            float* op = out + (size_t)row * 24;
            #pragma unroll
            for (int c = 0; c < 24; ++c) op[c] = ((chosen >> c) & 1u) ? 1.0f : 0.0f;
        }
        __syncthreads();
    }
}

// smem (bytes):
//   Ahi [128r x 256k] f16 tiled @ 0 (65536); Alo @ 65536 (65536)
//   B 2 bufs x (hi 16K + lo 16K) @ 131072 (65536)
//   overlays after layer 2: W3s @ 131072 (24576), logit_s @ 155648 (12800)
#define OFF_AHI 0
#define OFF_ALO 65536
#define OFF_B   131072
#define B_STRIDE 32768
#define OFF_W3  131072
#define OFF_LG  155648
#define SMEM_BYTES 196608

__global__ void __launch_bounds__(256, 1) fused_mlp_hmma(
    const float* __restrict__ X,
    const float* __restrict__ b1, const float* __restrict__ b2,
    const float* __restrict__ W3, const float* __restrict__ b3,
    float* __restrict__ out)
{
    extern __shared__ char smc[];
    __half* Ahi = (__half*)(smc + OFF_AHI);
    __half* Alo = (__half*)(smc + OFF_ALO);

    const int tid  = threadIdx.x;
    const int w    = tid >> 5;
    const int lane = tid & 31;
    const int bm0  = blockIdx.x * 128;
    const uint32_t smb = smem_u32(smc);

    const int rg = w >> 1;
    const int cg = w & 1;

    // ---- X -> A hi/lo tiles ----
    #pragma unroll
    for (int u = 0; u < 32; ++u) {
        int i = tid + u * 256;
        int row = i >> 6, kq = (i & 63) * 4;
        float4 v = *(const float4*)(X + (size_t)(bm0 + row) * 256 + kq);
        int off = ((row >> 3) * 32 + (kq >> 3)) * 64 + (row & 7) * 8 + (kq & 7);
        __half hx = __float2half_rn(v.x), hy = __float2half_rn(v.y);
        __half hz = __float2half_rn(v.z), hw = __float2half_rn(v.w);
        *(__half2*)(Ahi + off)     = __halves2half2(hx, hy);
        *(__half2*)(Ahi + off + 2) = __halves2half2(hz, hw);
        *(__half2*)(Alo + off)     = __halves2half2(__float2half_rn(v.x - __half2float(hx)),
                                                    __float2half_rn(v.y - __half2float(hy)));
        *(__half2*)(Alo + off + 2) = __halves2half2(__float2half_rn(v.z - __half2float(hz)),
                                                    __float2half_rn(v.w - __half2float(hw)));
    }
    {
        const float4* shi = (const float4*)(g_Bhi[0]);
        const float4* slo = (const float4*)(g_Blo[0]);
        float4* dhi = (float4*)(smc + OFF_B);
        float4* dlo = (float4*)(smc + OFF_B + 16384);
        #pragma unroll
        for (int u = 0; u < 4; ++u) { int i = tid + u * 256; dhi[i] = shi[i]; dlo[i] = slo[i]; }
    }
    __syncthreads();

    const int m = lane >> 3, r = lane & 7;
    const uint32_t aTail0 = (uint32_t)(((rg * 4 + 0 + (m & 1)) * 32 + (m >> 1)) * 128 + r * 16);
    const uint32_t aTail1 = (uint32_t)(((rg * 4 + 2 + (m & 1)) * 32 + (m >> 1)) * 128 + r * 16);
    const uint32_t aHi0 = smb + OFF_AHI + aTail0;
    const uint32_t aHi1 = smb + OFF_AHI + aTail1;
    const uint32_t aLo0 = smb + OFF_ALO + aTail0;
    const uint32_t aLo1 = smb + OFF_ALO + aTail1;
    const uint32_t bBase = (uint32_t)(((m >> 1) * 4 + (m & 1)) * 128 + r * 16);

    const int g   = lane >> 2;
    const int tig = lane & 3;

    float acc[2][16][4];

    #pragma unroll 1
    for (int l = 0; l < 2; ++l) {
        #pragma unroll
        for (int t = 0; t < 2; ++t)
            #pragma unroll
            for (int nt = 0; nt < 16; ++nt)
                #pragma unroll
                for (int q = 0; q < 4; ++q) acc[t][nt][q] = 0.0f;

        #pragma unroll 1
        for (int kc = 0; kc < 8; ++kc) {
            const int c   = l * 8 + kc;
            const int buf = c & 1;
            if (c < 15) {
                const int cn = c + 1;
                const float4* shi = (const float4*)(g_Bhi[cn >> 3] + (cn & 7) * 8192);
                const float4* slo = (const float4*)(g_Blo[cn >> 3] + (cn & 7) * 8192);
                float4* dhi = (float4*)(smc + OFF_B + (buf ^ 1) * B_STRIDE);
                float4* dlo = (float4*)(smc + OFF_B + (buf ^ 1) * B_STRIDE + 16384);
                #pragma unroll
                for (int u = 0; u < 4; ++u) { int i = tid + u * 256; dhi[i] = shi[i]; dlo[i] = slo[i]; }
            }
            const uint32_t bhB = smb + OFF_B + buf * B_STRIDE + bBase + cg * 8192;
            const uint32_t blB = bhB + 16384;
            #pragma unroll
            for (int ks = 0; ks < 2; ++ks) {
                const uint32_t koff = (uint32_t)((kc * 2 + ks) * 256);
                uint32_t ah[2][4], al[2][4];
                LDSM4(ah[0], aHi0 + koff);
                LDSM4(ah[1], aHi1 + koff);
                LDSM4(al[0], aLo0 + koff);
                LDSM4(al[1], aLo1 + koff);
                #pragma unroll
                for (int nt2 = 0; nt2 < 8; ++nt2) {
                    uint32_t bh[4], bl[4];
                    LDSM4(bh, bhB + nt2 * 1024 + ks * 256);
                    LDSM4(bl, blB + nt2 * 1024 + ks * 256);
                    #pragma unroll
                    for (int t = 0; t < 2; ++t) {
                        mma_f16(acc[t][2 * nt2],     ah[t], bh[0], bh[1]);
                        mma_f16(acc[t][2 * nt2],     ah[t], bl[0], bl[1]);
                        mma_f16(acc[t][2 * nt2],     al[t], bh[0], bh[1]);
                        mma_f16(acc[t][2 * nt2 + 1], ah[t], bh[2], bh[3]);
                        mma_f16(acc[t][2 * nt2 + 1], ah[t], bl[2], bl[3]);
                        mma_f16(acc[t][2 * nt2 + 1], al[t], bh[2], bh[3]);
                    }
                }
            }
            __syncthreads();
        }

        // ---- epilogue: bias + relu + fp16 split -> A (in place) ----
        const float* bias = l ? b2 : b1;
        #pragma unroll
        for (int t = 0; t < 2; ++t) {
            const int r0 = rg * 32 + t * 16 + g;
            const int r1 = r0 + 8;
            #pragma unroll
            for (int nt = 0; nt < 16; ++nt) {
                int c0 = cg * 128 + nt * 8 + 2 * tig;
                float2 bb = __ldg((const float2*)(bias + c0));
                float v0 = fmaxf(acc[t][nt][0] + bb.x, 0.0f);
                float v1 = fmaxf(acc[t][nt][1] + bb.y, 0.0f);
                float v2 = fmaxf(acc[t][nt][2] + bb.x, 0.0f);
                float v3 = fmaxf(acc[t][nt][3] + bb.y, 0.0f);
                int off0 = ((r0 >> 3) * 32 + (c0 >> 3)) * 64 + (r0 & 7) * 8 + (c0 & 7);
                int off1 = ((r1 >> 3) * 32 + (c0 >> 3)) * 64 + (r1 & 7) * 8 + (c0 & 7);
                __half h0 = __float2half_rn(v0), h1 = __float2half_rn(v1);
                __half h2 = __float2half_rn(v2), h3 = __float2half_rn(v3);
                *(__half2*)(Ahi + off0) = __halves2half2(h0, h1);
                *(__half2*)(Ahi + off1) = __halves2half2(h2, h3);
                *(__half2*)(Alo + off0) = __halves2half2(__float2half_rn(v0 - __half2float(h0)),
                                                         __float2half_rn(v1 - __half2float(h1)));
                *(__half2*)(Alo + off1) = __halves2half2(__float2half_rn(v2 - __half2float(h2)),
                                                         __float2half_rn(v3 - __half2float(h3)));
            }
        }
        __syncthreads();
    }

    // ---- stage W3 (fp32) into dead B region ----
    {
        float* W3s = (float*)(smc + OFF_W3);
        #pragma unroll
        for (int u = 0; u < 6; ++u) {
            int i = tid + u * 256;
            ((float4*)W3s)[i] = ((const float4*)W3)[i];
        }
    }
    __syncthreads();

    // ---- Layer 3: logits = h @ W3 + b3 (FFMA2, h = hi+lo) ----
    {
        float* logit_s = (float*)(smc + OFF_LG);
        const ULL* W3s64 = (const ULL*)(smc + OFF_W3);
        const int rp = tid & 63;
        const int gq = tid >> 6;
        const int ra = rp, rb = rp + 64;
        const int baseA = (ra >> 3) * 2048 + (ra & 7) * 8;
        const int baseB = (rb >> 3) * 2048 + (rb & 7) * 8;
        ULL a3[2][3];
        #pragma unroll
        for (int j = 0; j < 3; ++j) { a3[0][j] = 0ULL; a3[1][j] = 0ULL; }
        #pragma unroll 4
        for (int kt = 0; kt < 32; ++kt) {
            uint4 h0 = *(const uint4*)(Ahi + baseA + kt * 64);
            uint4 l0 = *(const uint4*)(Alo + baseA + kt * 64);
            uint4 h1 = *(const uint4*)(Ahi + baseB + kt * 64);
            uint4 l1 = *(const uint4*)(Alo + baseB + kt * 64);
            float x0[8], x1[8];
            const __half2* hp0 = (const __half2*)&h0;
            const __half2* lp0 = (const __half2*)&l0;
            const __half2* hp1 = (const __half2*)&h1;
            const __half2* lp1 = (const __half2*)&l1;
            #pragma unroll
            for (int q = 0; q < 4; ++q) {
                float2 a = __half22float2(hp0[q]), b = __half22float2(lp0[q]);
                x0[2*q] = a.x + b.x; x0[2*q+1] = a.y + b.y;
                float2 cpp = __half22float2(hp1[q]), d = __half22float2(lp1[q]);
                x1[2*q] = cpp.x + d.x; x1[2*q+1] = cpp.y + d.y;
            }
            #pragma unroll
            for (int kk = 0; kk < 8; ++kk) {
                int k = kt * 8 + kk;
                ULL a0 = f2dup(x0[kk]);
                ULL a1 = f2dup(x1[kk]);
                #pragma unroll
                for (int j = 0; j < 3; ++j) {
                    ULL wv = W3s64[k * 12 + 3 * gq + j];
                    a3[0][j] = ffma2(a0, wv, a3[0][j]);
                    a3[1][j] = ffma2(a1, wv, a3[1][j]);
                }
            }
        }
        #pragma unroll
        for (int j = 0; j < 3; ++j) {
            float2 bb = ((const float2*)b3)[3 * gq + j];
            float2 v0 = f2unpack(a3[0][j]);
            float2 v1 = f2unpack(a3[1][j]);
            logit_s[ra * 25 + 6 * gq + 2 * j]     = v0.x + bb.x;
            logit_s[ra * 25 + 6 * gq + 2 * j + 1] = v0.y + bb.y;
            logit_s[rb * 25 + 6 * gq + 2 * j]     = v1.x + bb.x;
            logit_s[rb * 25 + 6 * gq + 2 * j + 1] = v1.y + bb.y;
        }
    }
    __syncthreads();

    // ---- top-6 of 22 selected + borderline flagging + write ----
    if (tid < 128) {
        const float* logit_s = (const float*)(smc + OFF_LG);
        const int row = bm0 + tid;
        float v[24];
        #pragma unroll
        for (int c = 0; c < 24; ++c) v[c] = logit_s[tid * 25 + c];

        unsigned chosen = 1u | (1u << 12);
        float lastBest = 0.0f;
        #pragma unroll
        for (int it = 0; it < 6; ++it) {
            float best = -3.402823466e38f;
            int bi = 1;
            #pragma unroll
            for (int c = 1; c < 24; ++c) {
                if (c == 12) continue;
                bool free_ = !((chosen >> c) & 1u);
                if (free_ && v[c] > best) { best = v[c]; bi = c; }  // strict >: lower index wins ties
            }
            chosen |= (1u << bi);
            lastBest = best;
        }
        float v7 = -3.402823466e38f;
        #pragma unroll
        for (int c = 1; c < 24; ++c) {
            if (c == 12) continue;
            if (!((chosen >> c) & 1u)) v7 = fmaxf(v7, v[c]);
        }
        if (lastBest - v7 < TAU) {
            int idx = atomicAdd(&g_cnt, 1);
            g_list[idx] = row;
        }

        float o[24];
        #pragma unroll
        for (int c = 0; c < 24; ++c) o[c] = ((chosen >> c) & 1u) ? 1.0f : 0.0f;
        float4* op = (float4*)(out + (size_t)row * 24);
        #pragma unroll
        for (int g2 = 0; g2 < 6; ++g2)
            op[g2] = make_float4(o[4 * g2], o[4 * g2 + 1], o[4 * g2 + 2], o[4 * g2 + 3]);
    }
}

extern "C" void kernel_launch(void* const* d_in, const int* in_sizes, int n_in,
                              void* d_out, int out_size) {
    const float* X  = (const float*)d_in[0];
    const float* W1 = (const float*)d_in[1];
    const float* b1 = (const float*)d_in[2];
    const float* W2 = (const float*)d_in[3];
    const float* b2 = (const float*)d_in[4];
    const float* W3 = (const float*)d_in[5];
    const float* b3 = (const float*)d_in[6];
    float* out = (float*)d_out;

    int B = in_sizes[0] / 256;

    prep_kernel<<<256, 256>>>(W1, W2);

    cudaFuncSetAttribute(fused_mlp_hmma, cudaFuncAttributeMaxDynamicSharedMemorySize, SMEM_BYTES);
    fused_mlp_hmma<<<B / 128, 256, SMEM_BYTES>>>(X, b1, b2, W3, b3, out);

    fixup_kernel<<<1480, 256>>>(X, W1, b1, W2, b2, W3, b3, out);
}

// round 16
// speedup vs baseline: 1.6996x; 1.0198x over previous
#include <cuda_runtime.h>
#include <cuda_fp16.h>
#include <cstdint>

typedef unsigned long long ULL;

__device__ __forceinline__ uint32_t smem_u32(const void* p){
    uint32_t a;
    asm("{ .reg .u64 t; cvta.to.shared.u64 t, %1; cvt.u32.u64 %0, t; }" : "=r"(a) : "l"(p));
    return a;
}
__device__ __forceinline__ ULL f2dup(float x) {
    ULL r; asm("mov.b64 %0, {%1,%1};" : "=l"(r) : "f"(x)); return r;
}
__device__ __forceinline__ float2 f2unpack(ULL v) {
    float2 r; asm("mov.b64 {%0,%1}, %2;" : "=f"(r.x), "=f"(r.y) : "l"(v)); return r;
}
__device__ __forceinline__ ULL ffma2(ULL a, ULL b, ULL c) {
    ULL d; asm("fma.rn.f32x2 %0, %1, %2, %3;" : "=l"(d) : "l"(a), "l"(b), "l"(c)); return d;
}

#define LDSM4(rg, addr) \
    asm volatile("ldmatrix.sync.aligned.m8n8.x4.shared.b16 {%0,%1,%2,%3}, [%4];" \
        : "=r"((rg)[0]), "=r"((rg)[1]), "=r"((rg)[2]), "=r"((rg)[3]) : "r"(addr))

__device__ __forceinline__ void mma_f16(float* c, const uint32_t* a, uint32_t b0, uint32_t b1){
    asm volatile("mma.sync.aligned.m16n8k16.row.col.f32.f16.f16.f32 "
        "{%0,%1,%2,%3}, {%4,%5,%6,%7}, {%8,%9}, {%0,%1,%2,%3};"
        : "+f"(c[0]), "+f"(c[1]), "+f"(c[2]), "+f"(c[3])
        : "r"(a[0]), "r"(a[1]), "r"(a[2]), "r"(a[3]), "r"(b0), "r"(b1));
}

#define TAU 3e-5f

__device__ __half g_Bhi[2][65536];
__device__ __half g_Blo[2][65536];

__global__ void prep_kernel(const float* __restrict__ W1, const float* __restrict__ W2){
    int i = blockIdx.x * 256 + threadIdx.x;   // 0..65535
    int k = i >> 8, n = i & 255;
    int dst = (k >> 5) * 8192 + ((n >> 3) * 4 + ((k >> 3) & 3)) * 64 + (n & 7) * 8 + (k & 7);
    {
        float v = W1[k * 256 + n];
        __half hi = __float2half_rn(v);
        g_Bhi[0][dst] = hi;
        g_Blo[0][dst] = __float2half_rn(v - __half2float(hi));
    }
    {
        float v = W2[k * 256 + n];
        __half hi = __float2half_rn(v);
        g_Bhi[1][dst] = hi;
        g_Blo[1][dst] = __float2half_rn(v - __half2float(hi));
    }
}

// smem (bytes):
//   Ahi [128r x 256k] f16 tiled @ 0 (65536); Alo @ 65536 (65536)
//   B 2 bufs x (hi 16K + lo 16K) @ 131072 (65536)
//   overlays after layer 2: W3s @ 131072 (24576), logit_s @ 155648 (12800)
//   overlay for inline fixup (Ahi dead after L3): xa/xb/lg2 @ 0
#define OFF_AHI 0
#define OFF_ALO 65536
#define OFF_B   131072
#define B_STRIDE 32768
#define OFF_W3  131072
#define OFF_LG  155648
#define SMEM_BYTES 196608

__global__ void __launch_bounds__(256, 1) fused_mlp_hmma(
    const float* __restrict__ X,
    const float* __restrict__ W1f, const float* __restrict__ b1,
    const float* __restrict__ W2f, const float* __restrict__ b2,
    const float* __restrict__ W3, const float* __restrict__ b3,
    float* __restrict__ out)
{
    extern __shared__ char smc[];
    __half* Ahi = (__half*)(smc + OFF_AHI);
    __half* Alo = (__half*)(smc + OFF_ALO);

    __shared__ int s_cnt;
    __shared__ unsigned char s_list[128];

    const int tid  = threadIdx.x;
    const int w    = tid >> 5;
    const int lane = tid & 31;
    const int bm0  = blockIdx.x * 128;
    const uint32_t smb = smem_u32(smc);

    const int rg = w >> 1;
    const int cg = w & 1;

    // ---- X -> A hi/lo tiles ----
    #pragma unroll
    for (int u = 0; u < 32; ++u) {
        int i = tid + u * 256;
        int row = i >> 6, kq = (i & 63) * 4;
        float4 v = *(const float4*)(X + (size_t)(bm0 + row) * 256 + kq);
        int off = ((row >> 3) * 32 + (kq >> 3)) * 64 + (row & 7) * 8 + (kq & 7);
        __half hx = __float2half_rn(v.x), hy = __float2half_rn(v.y);
        __half hz = __float2half_rn(v.z), hw = __float2half_rn(v.w);
        *(__half2*)(Ahi + off)     = __halves2half2(hx, hy);
        *(__half2*)(Ahi + off + 2) = __halves2half2(hz, hw);
        *(__half2*)(Alo + off)     = __halves2half2(__float2half_rn(v.x - __half2float(hx)),
                                                    __float2half_rn(v.y - __half2float(hy)));
        *(__half2*)(Alo + off + 2) = __halves2half2(__float2half_rn(v.z - __half2float(hz)),
                                                    __float2half_rn(v.w - __half2float(hw)));
    }
    {
        const float4* shi = (const float4*)(g_Bhi[0]);
        const float4* slo = (const float4*)(g_Blo[0]);
        float4* dhi = (float4*)(smc + OFF_B);
        float4* dlo = (float4*)(smc + OFF_B + 16384);
        #pragma unroll
        for (int u = 0; u < 4; ++u) { int i = tid + u * 256; dhi[i] = shi[i]; dlo[i] = slo[i]; }
    }
    if (tid == 0) s_cnt = 0;
    __syncthreads();

    const int m = lane >> 3, r = lane & 7;
    const uint32_t aTail0 = (uint32_t)(((rg * 4 + 0 + (m & 1)) * 32 + (m >> 1)) * 128 + r * 16);
    const uint32_t aTail1 = (uint32_t)(((rg * 4 + 2 + (m & 1)) * 32 + (m >> 1)) * 128 + r * 16);
    const uint32_t aHi0 = smb + OFF_AHI + aTail0;
    const uint32_t aHi1 = smb + OFF_AHI + aTail1;
    const uint32_t aLo0 = smb + OFF_ALO + aTail0;
    const uint32_t aLo1 = smb + OFF_ALO + aTail1;
    const uint32_t bBase = (uint32_t)(((m >> 1) * 4 + (m & 1)) * 128 + r * 16);

    const int g   = lane >> 2;
    const int tig = lane & 3;

    float acc[2][16][4];

    #pragma unroll 1
    for (int l = 0; l < 2; ++l) {
        #pragma unroll
        for (int t = 0; t < 2; ++t)
            #pragma unroll
            for (int nt = 0; nt < 16; ++nt)
                #pragma unroll
                for (int q = 0; q < 4; ++q) acc[t][nt][q] = 0.0f;

        #pragma unroll 1
        for (int kc = 0; kc < 8; ++kc) {
            const int c   = l * 8 + kc;
            const int buf = c & 1;
            if (c < 15) {
                const int cn = c + 1;
                const float4* shi = (const float4*)(g_Bhi[cn >> 3] + (cn & 7) * 8192);
                const float4* slo = (const float4*)(g_Blo[cn >> 3] + (cn & 7) * 8192);
                float4* dhi = (float4*)(smc + OFF_B + (buf ^ 1) * B_STRIDE);
                float4* dlo = (float4*)(smc + OFF_B + (buf ^ 1) * B_STRIDE + 16384);
                #pragma unroll
                for (int u = 0; u < 4; ++u) { int i = tid + u * 256; dhi[i] = shi[i]; dlo[i] = slo[i]; }
            }
            const uint32_t bhB = smb + OFF_B + buf * B_STRIDE + bBase + cg * 8192;
            const uint32_t blB = bhB + 16384;
            #pragma unroll
            for (int ks = 0; ks < 2; ++ks) {
                const uint32_t koff = (uint32_t)((kc * 2 + ks) * 256);
                uint32_t ah[2][4], al[2][4];
                LDSM4(ah[0], aHi0 + koff);
                LDSM4(ah[1], aHi1 + koff);
                LDSM4(al[0], aLo0 + koff);
                LDSM4(al[1], aLo1 + koff);
                #pragma unroll
                for (int nt2 = 0; nt2 < 8; ++nt2) {
                    uint32_t bh[4], bl[4];
                    LDSM4(bh, bhB + nt2 * 1024 + ks * 256);
                    LDSM4(bl, blB + nt2 * 1024 + ks * 256);
                    #pragma unroll
                    for (int t = 0; t < 2; ++t) {
                        mma_f16(acc[t][2 * nt2],     ah[t], bh[0], bh[1]);
                        mma_f16(acc[t][2 * nt2],     ah[t], bl[0], bl[1]);
                        mma_f16(acc[t][2 * nt2],     al[t], bh[0], bh[1]);
                        mma_f16(acc[t][2 * nt2 + 1], ah[t], bh[2], bh[3]);
                        mma_f16(acc[t][2 * nt2 + 1], ah[t], bl[2], bl[3]);
                        mma_f16(acc[t][2 * nt2 + 1], al[t], bh[2], bh[3]);
                    }
                }
            }
            __syncthreads();
        }

        // ---- epilogue: bias + relu + fp16 split -> A (in place) ----
        const float* bias = l ? b2 : b1;
        #pragma unroll
        for (int t = 0; t < 2; ++t) {
            const int r0 = rg * 32 + t * 16 + g;
            const int r1 = r0 + 8;
            #pragma unroll
            for (int nt = 0; nt < 16; ++nt) {
                int c0 = cg * 128 + nt * 8 + 2 * tig;
                float2 bb = __ldg((const float2*)(bias + c0));
                float v0 = fmaxf(acc[t][nt][0] + bb.x, 0.0f);
                float v1 = fmaxf(acc[t][nt][1] + bb.y, 0.0f);
                float v2 = fmaxf(acc[t][nt][2] + bb.x, 0.0f);
                float v3 = fmaxf(acc[t][nt][3] + bb.y, 0.0f);
                int off0 = ((r0 >> 3) * 32 + (c0 >> 3)) * 64 + (r0 & 7) * 8 + (c0 & 7);
                int off1 = ((r1 >> 3) * 32 + (c0 >> 3)) * 64 + (r1 & 7) * 8 + (c0 & 7);
                __half h0 = __float2half_rn(v0), h1 = __float2half_rn(v1);
                __half h2 = __float2half_rn(v2), h3 = __float2half_rn(v3);
                *(__half2*)(Ahi + off0) = __halves2half2(h0, h1);
                *(__half2*)(Ahi + off1) = __halves2half2(h2, h3);
                *(__half2*)(Alo + off0) = __halves2half2(__float2half_rn(v0 - __half2float(h0)),
                                                         __float2half_rn(v1 - __half2float(h1)));
                *(__half2*)(Alo + off1) = __halves2half2(__float2half_rn(v2 - __half2float(h2)),
                                                         __float2half_rn(v3 - __half2float(h3)));
            }
        }
        __syncthreads();
    }

    // ---- stage W3 (fp32) into dead B region ----
    {
        float* W3s = (float*)(smc + OFF_W3);
        #pragma unroll
        for (int u = 0; u < 6; ++u) {
            int i = tid + u * 256;
            ((float4*)W3s)[i] = ((const float4*)W3)[i];
        }
    }
    __syncthreads();

    // ---- Layer 3: logits = h @ W3 + b3 (FFMA2, h = hi+lo) ----
    {
        float* logit_s = (float*)(smc + OFF_LG);
        const ULL* W3s64 = (const ULL*)(smc + OFF_W3);
        const int rp = tid & 63;
        const int gq = tid >> 6;
        const int ra = rp, rb = rp + 64;
        const int baseA = (ra >> 3) * 2048 + (ra & 7) * 8;
        const int baseB = (rb >> 3) * 2048 + (rb & 7) * 8;
        ULL a3[2][3];
        #pragma unroll
        for (int j = 0; j < 3; ++j) { a3[0][j] = 0ULL; a3[1][j] = 0ULL; }
        #pragma unroll 4
        for (int kt = 0; kt < 32; ++kt) {
            uint4 h0 = *(const uint4*)(Ahi + baseA + kt * 64);
            uint4 l0 = *(const uint4*)(Alo + baseA + kt * 64);
            uint4 h1 = *(const uint4*)(Ahi + baseB + kt * 64);
            uint4 l1 = *(const uint4*)(Alo + baseB + kt * 64);
            float x0[8], x1[8];
            const __half2* hp0 = (const __half2*)&h0;
            const __half2* lp0 = (const __half2*)&l0;
            const __half2* hp1 = (const __half2*)&h1;
            const __half2* lp1 = (const __half2*)&l1;
            #pragma unroll
            for (int q = 0; q < 4; ++q) {
                float2 a = __half22float2(hp0[q]), b = __half22float2(lp0[q]);
                x0[2*q] = a.x + b.x; x0[2*q+1] = a.y + b.y;
                float2 cpp = __half22float2(hp1[q]), d = __half22float2(lp1[q]);
                x1[2*q] = cpp.x + d.x; x1[2*q+1] = cpp.y + d.y;
            }
            #pragma unroll
            for (int kk = 0; kk < 8; ++kk) {
                int k = kt * 8 + kk;
                ULL a0 = f2dup(x0[kk]);
                ULL a1 = f2dup(x1[kk]);
                #pragma unroll
                for (int j = 0; j < 3; ++j) {
                    ULL wv = W3s64[k * 12 + 3 * gq + j];
                    a3[0][j] = ffma2(a0, wv, a3[0][j]);
                    a3[1][j] = ffma2(a1, wv, a3[1][j]);
                }
            }
        }
        #pragma unroll
        for (int j = 0; j < 3; ++j) {
            float2 bb = ((const float2*)b3)[3 * gq + j];
            float2 v0 = f2unpack(a3[0][j]);
            float2 v1 = f2unpack(a3[1][j]);
            logit_s[ra * 25 + 6 * gq + 2 * j]     = v0.x + bb.x;
            logit_s[ra * 25 + 6 * gq + 2 * j + 1] = v0.y + bb.y;
            logit_s[rb * 25 + 6 * gq + 2 * j]     = v1.x + bb.x;
            logit_s[rb * 25 + 6 * gq + 2 * j + 1] = v1.y + bb.y;
        }
    }
    __syncthreads();

    // ---- top-6 of 22 selected + borderline flagging (per-CTA) + write ----
    if (tid < 128) {
        const float* logit_s = (const float*)(smc + OFF_LG);
        const int row = bm0 + tid;
        float v[24];
        #pragma unroll
        for (int c = 0; c < 24; ++c) v[c] = logit_s[tid * 25 + c];

        unsigned chosen = 1u | (1u << 12);
        float lastBest = 0.0f;
        #pragma unroll
        for (int it = 0; it < 6; ++it) {
            float best = -3.402823466e38f;
            int bi = 1;
            #pragma unroll
            for (int c = 1; c < 24; ++c) {
                if (c == 12) continue;
                bool free_ = !((chosen >> c) & 1u);
                if (free_ && v[c] > best) { best = v[c]; bi = c; }  // strict >: lower index wins ties
            }
            chosen |= (1u << bi);
            lastBest = best;
        }
        float v7 = -3.402823466e38f;
        #pragma unroll
        for (int c = 1; c < 24; ++c) {
            if (c == 12) continue;
            if (!((chosen >> c) & 1u)) v7 = fmaxf(v7, v[c]);
        }
        if (lastBest - v7 < TAU) {
            int idx = atomicAdd(&s_cnt, 1);
            s_list[idx] = (unsigned char)tid;
        }

        float o[24];
        #pragma unroll
        for (int c = 0; c < 24; ++c) o[c] = ((chosen >> c) & 1u) ? 1.0f : 0.0f;
        float4* op = (float4*)(out + (size_t)row * 24);
        #pragma unroll
        for (int g2 = 0; g2 < 6; ++g2)
            op[g2] = make_float4(o[4 * g2], o[4 * g2 + 1], o[4 * g2 + 2], o[4 * g2 + 3]);
    }
    __syncthreads();

    // ---- inline exact fp32 fixup for this CTA's flagged rows ----
    // (Ahi/Alo dead; overlay xa/xb/lg2 at smem offset 0. Same numerics as
    //  the previously validated fixup kernel: k-sequential fp32 FMA.)
    const int fcnt = s_cnt;
    if (fcnt > 0) {
        float* xa  = (float*)smc;
        float* xb  = xa + 256;
        float* lg2 = xb + 256;
        const int j = tid;
        #pragma unroll 1
        for (int i = 0; i < fcnt; ++i) {
            const int row = bm0 + (int)s_list[i];
            xa[j] = X[(size_t)row * 256 + j];
            __syncthreads();
            {
                float s = 0.0f;
                #pragma unroll 32
                for (int k = 0; k < 256; ++k) s = fmaf(xa[k], W1f[(size_t)k * 256 + j], s);
                xb[j] = fmaxf(s + b1[j], 0.0f);
            }
            __syncthreads();
            {
                float s = 0.0f;
                #pragma unroll 32
                for (int k = 0; k < 256; ++k) s = fmaf(xb[k], W2f[(size_t)k * 256 + j], s);
                xa[j] = fmaxf(s + b2[j], 0.0f);
            }
            __syncthreads();
            if (j < 24) {
                float s = 0.0f;
                #pragma unroll 32
                for (int k = 0; k < 256; ++k) s = fmaf(xa[k], W3[(size_t)k * 24 + j], s);
                lg2[j] = s + b3[j];
            }
            __syncthreads();
            if (j == 0) {
                float v[24];
                #pragma unroll
                for (int c = 0; c < 24; ++c) v[c] = lg2[c];
                unsigned chosen = 1u | (1u << 12);
                #pragma unroll
                for (int it = 0; it < 6; ++it) {
                    float best = -3.402823466e38f;
                    int bi = 1;
                    #pragma unroll
                    for (int c = 1; c < 24; ++c) {
                        if (c == 12) continue;
                        bool free_ = !((chosen >> c) & 1u);
                        if (free_ && v[c] > best) { best = v[c]; bi = c; }
                    }
                    chosen |= (1u << bi);
                }
                float* op = out + (size_t)row * 24;
                #pragma unroll
                for (int c = 0; c < 24; ++c) op[c] = ((chosen >> c) & 1u) ? 1.0f : 0.0f;
            }
            __syncthreads();
        }
    }
}

extern "C" void kernel_launch(void* const* d_in, const int* in_sizes, int n_in,
                              void* d_out, int out_size) {
    const float* X  = (const float*)d_in[0];
    const float* W1 = (const float*)d_in[1];
    const float* b1 = (const float*)d_in[2];
    const float* W2 = (const float*)d_in[3];
    const float* b2 = (const float*)d_in[4];
    const float* W3 = (const float*)d_in[5];
    const float* b3 = (const float*)d_in[6];
    float* out = (float*)d_out;

    int B = in_sizes[0] / 256;

    prep_kernel<<<256, 256>>>(W1, W2);

    cudaFuncSetAttribute(fused_mlp_hmma, cudaFuncAttributeMaxDynamicSharedMemorySize, SMEM_BYTES);
    fused_mlp_hmma<<<B / 128, 256, SMEM_BYTES>>>(X, W1, b1, W2, b2, W3, b3, out);
}

// round 17
// speedup vs baseline: 1.7804x; 1.0476x over previous
#include <cuda_runtime.h>
#include <cuda_fp16.h>
#include <cstdint>

typedef unsigned long long ULL;

__device__ __forceinline__ uint32_t smem_u32(const void* p){
    uint32_t a;
    asm("{ .reg .u64 t; cvta.to.shared.u64 t, %1; cvt.u32.u64 %0, t; }" : "=r"(a) : "l"(p));
    return a;
}
__device__ __forceinline__ ULL f2dup(float x) {
    ULL r; asm("mov.b64 %0, {%1,%1};" : "=l"(r) : "f"(x)); return r;
}
__device__ __forceinline__ float2 f2unpack(ULL v) {
    float2 r; asm("mov.b64 {%0,%1}, %2;" : "=f"(r.x), "=f"(r.y) : "l"(v)); return r;
}
__device__ __forceinline__ ULL ffma2(ULL a, ULL b, ULL c) {
    ULL d; asm("fma.rn.f32x2 %0, %1, %2, %3;" : "=l"(d) : "l"(a), "l"(b), "l"(c)); return d;
}

#define LDSM4(rg, addr) \
    asm volatile("ldmatrix.sync.aligned.m8n8.x4.shared.b16 {%0,%1,%2,%3}, [%4];" \
        : "=r"((rg)[0]), "=r"((rg)[1]), "=r"((rg)[2]), "=r"((rg)[3]) : "r"(addr))

__device__ __forceinline__ void mma_f16(float* c, const uint32_t* a, uint32_t b0, uint32_t b1){
    asm volatile("mma.sync.aligned.m16n8k16.row.col.f32.f16.f16.f32 "
        "{%0,%1,%2,%3}, {%4,%5,%6,%7}, {%8,%9}, {%0,%1,%2,%3};"
        : "+f"(c[0]), "+f"(c[1]), "+f"(c[2]), "+f"(c[3])
        : "r"(a[0]), "r"(a[1]), "r"(a[2]), "r"(a[3]), "r"(b0), "r"(b1));
}

#define TAU 3e-5f

__device__ __half g_Bhi[2][65536];
__device__ __half g_Blo[2][65536];

__global__ void prep_kernel(const float* __restrict__ W1, const float* __restrict__ W2){
    int i = blockIdx.x * 256 + threadIdx.x;   // 0..65535
    int k = i >> 8, n = i & 255;
    int dst = (k >> 5) * 8192 + ((n >> 3) * 4 + ((k >> 3) & 3)) * 64 + (n & 7) * 8 + (k & 7);
    {
        float v = W1[k * 256 + n];
        __half hi = __float2half_rn(v);
        g_Bhi[0][dst] = hi;
        g_Blo[0][dst] = __float2half_rn(v - __half2float(hi));
    }
    {
        float v = W2[k * 256 + n];
        __half hi = __float2half_rn(v);
        g_Bhi[1][dst] = hi;
        g_Blo[1][dst] = __float2half_rn(v - __half2float(hi));
    }
}

// Per-CTA: 64 rows. smem (bytes):
//   Ahi [64r x 256k] f16 tiled @ 0 (32768); Alo @ 32768 (32768)
//   B single buf (hi 16K @65536, lo 16K @81920)          (32768)
//   overlays after layer 2 (B dead): W3s @ 65536 (24576), logit_s @ 90112 (6400)
//   overlay for inline fixup (Ahi dead): xa/xb/lg2 @ 0
#define OFF_AHI 0
#define OFF_ALO 32768
#define OFF_B   65536
#define OFF_W3  65536
#define OFF_LG  90112
#define SMEM_BYTES 98304

__global__ void __launch_bounds__(256, 2) fused_mlp_hmma(
    const float* __restrict__ X,
    const float* __restrict__ W1f, const float* __restrict__ b1,
    const float* __restrict__ W2f, const float* __restrict__ b2,
    const float* __restrict__ W3, const float* __restrict__ b3,
    float* __restrict__ out)
{
    extern __shared__ char smc[];
    __half* Ahi = (__half*)(smc + OFF_AHI);
    __half* Alo = (__half*)(smc + OFF_ALO);

    __shared__ int s_cnt;
    __shared__ unsigned char s_list[64];

    const int tid  = threadIdx.x;
    const int w    = tid >> 5;
    const int lane = tid & 31;
    const int bm0  = blockIdx.x * 64;
    const uint32_t smb = smem_u32(smc);

    const int rg = w >> 2;   // 0..1: rows rg*32..+31
    const int cg = w & 3;    // 0..3: cols cg*64..+63

    // ---- X -> A hi/lo tiles (64 rows) ----
    #pragma unroll
    for (int u = 0; u < 16; ++u) {
        int i = tid + u * 256;
        int row = i >> 6, kq = (i & 63) * 4;
        float4 v = *(const float4*)(X + (size_t)(bm0 + row) * 256 + kq);
        int off = ((row >> 3) * 32 + (kq >> 3)) * 64 + (row & 7) * 8 + (kq & 7);
        __half hx = __float2half_rn(v.x), hy = __float2half_rn(v.y);
        __half hz = __float2half_rn(v.z), hw = __float2half_rn(v.w);
        *(__half2*)(Ahi + off)     = __halves2half2(hx, hy);
        *(__half2*)(Ahi + off + 2) = __halves2half2(hz, hw);
        *(__half2*)(Alo + off)     = __halves2half2(__float2half_rn(v.x - __half2float(hx)),
                                                    __float2half_rn(v.y - __half2float(hy)));
        *(__half2*)(Alo + off + 2) = __halves2half2(__float2half_rn(v.z - __half2float(hz)),
                                                    __float2half_rn(v.w - __half2float(hw)));
    }
    if (tid == 0) s_cnt = 0;

    const int m = lane >> 3, r = lane & 7;
    const uint32_t aTail0 = (uint32_t)(((rg * 4 + 0 + (m & 1)) * 32 + (m >> 1)) * 128 + r * 16);
    const uint32_t aTail1 = (uint32_t)(((rg * 4 + 2 + (m & 1)) * 32 + (m >> 1)) * 128 + r * 16);
    const uint32_t aHi0 = smb + OFF_AHI + aTail0;
    const uint32_t aHi1 = smb + OFF_AHI + aTail1;
    const uint32_t aLo0 = smb + OFF_ALO + aTail0;
    const uint32_t aLo1 = smb + OFF_ALO + aTail1;
    const uint32_t bBase = (uint32_t)(((m >> 1) * 4 + (m & 1)) * 128 + r * 16);

    const int g   = lane >> 2;
    const int tig = lane & 3;

    float acc[2][8][4];

    #pragma unroll 1
    for (int l = 0; l < 2; ++l) {
        #pragma unroll
        for (int t = 0; t < 2; ++t)
            #pragma unroll
            for (int nt = 0; nt < 8; ++nt)
                #pragma unroll
                for (int q = 0; q < 4; ++q) acc[t][nt][q] = 0.0f;

        #pragma unroll 1
        for (int kc = 0; kc < 8; ++kc) {
            const int c = l * 8 + kc;
            __syncthreads();   // previous chunk fully consumed
            {
                const float4* shi = (const float4*)(g_Bhi[c >> 3] + (c & 7) * 8192);
                const float4* slo = (const float4*)(g_Blo[c >> 3] + (c & 7) * 8192);
                float4* dhi = (float4*)(smc + OFF_B);
                float4* dlo = (float4*)(smc + OFF_B + 16384);
                #pragma unroll
                for (int u = 0; u < 4; ++u) { int i = tid + u * 256; dhi[i] = shi[i]; dlo[i] = slo[i]; }
            }
            __syncthreads();
            const uint32_t bhB = smb + OFF_B + bBase + cg * 4096;
            const uint32_t blB = bhB + 16384;
            #pragma unroll
            for (int ks = 0; ks < 2; ++ks) {
                const uint32_t koff = (uint32_t)((kc * 2 + ks) * 256);
                uint32_t ah[2][4], al[2][4];
                LDSM4(ah[0], aHi0 + koff);
                LDSM4(ah[1], aHi1 + koff);
                LDSM4(al[0], aLo0 + koff);
                LDSM4(al[1], aLo1 + koff);
                #pragma unroll
                for (int nt2 = 0; nt2 < 4; ++nt2) {
                    uint32_t bh[4], bl[4];
                    LDSM4(bh, bhB + nt2 * 1024 + ks * 256);
                    LDSM4(bl, blB + nt2 * 1024 + ks * 256);
                    #pragma unroll
                    for (int t = 0; t < 2; ++t) {
                        mma_f16(acc[t][2 * nt2],     ah[t], bh[0], bh[1]);
                        mma_f16(acc[t][2 * nt2],     ah[t], bl[0], bl[1]);
                        mma_f16(acc[t][2 * nt2],     al[t], bh[0], bh[1]);
                        mma_f16(acc[t][2 * nt2 + 1], ah[t], bh[2], bh[3]);
                        mma_f16(acc[t][2 * nt2 + 1], ah[t], bl[2], bl[3]);
                        mma_f16(acc[t][2 * nt2 + 1], al[t], bh[2], bh[3]);
                    }
                }
            }
        }
        __syncthreads();

        // ---- epilogue: bias + relu + fp16 split -> A (in place) ----
        const float* bias = l ? b2 : b1;
        #pragma unroll
        for (int t = 0; t < 2; ++t) {
            const int r0 = rg * 32 + t * 16 + g;
            const int r1 = r0 + 8;
            #pragma unroll
            for (int nt = 0; nt < 8; ++nt) {
                int c0 = cg * 64 + nt * 8 + 2 * tig;
                float2 bb = __ldg((const float2*)(bias + c0));
                float v0 = fmaxf(acc[t][nt][0] + bb.x, 0.0f);
                float v1 = fmaxf(acc[t][nt][1] + bb.y, 0.0f);
                float v2 = fmaxf(acc[t][nt][2] + bb.x, 0.0f);
                float v3 = fmaxf(acc[t][nt][3] + bb.y, 0.0f);
                int off0 = ((r0 >> 3) * 32 + (c0 >> 3)) * 64 + (r0 & 7) * 8 + (c0 & 7);
                int off1 = ((r1 >> 3) * 32 + (c0 >> 3)) * 64 + (r1 & 7) * 8 + (c0 & 7);
                __half h0 = __float2half_rn(v0), h1 = __float2half_rn(v1);
                __half h2 = __float2half_rn(v2), h3 = __float2half_rn(v3);
                *(__half2*)(Ahi + off0) = __halves2half2(h0, h1);
                *(__half2*)(Ahi + off1) = __halves2half2(h2, h3);
                *(__half2*)(Alo + off0) = __halves2half2(__float2half_rn(v0 - __half2float(h0)),
                                                         __float2half_rn(v1 - __half2float(h1)));
                *(__half2*)(Alo + off1) = __halves2half2(__float2half_rn(v2 - __half2float(h2)),
                                                         __float2half_rn(v3 - __half2float(h3)));
            }
        }
        __syncthreads();
    }

    // ---- stage W3 (fp32) into dead B region ----
    {
        float* W3s = (float*)(smc + OFF_W3);
        #pragma unroll
        for (int u = 0; u < 6; ++u) {
            int i = tid + u * 256;
            ((float4*)W3s)[i] = ((const float4*)W3)[i];
        }
    }
    __syncthreads();

    // ---- Layer 3: logits = h @ W3 + b3 (FFMA2, h = hi+lo, 1 row/thread) ----
    {
        float* logit_s = (float*)(smc + OFF_LG);
        const ULL* W3s64 = (const ULL*)(smc + OFF_W3);
        const int rp = tid & 63;
        const int gq = tid >> 6;
        const int baseA = (rp >> 3) * 2048 + (rp & 7) * 8;
        ULL a3[3];
        #pragma unroll
        for (int j = 0; j < 3; ++j) a3[j] = 0ULL;
        #pragma unroll 4
        for (int kt = 0; kt < 32; ++kt) {
            uint4 h0 = *(const uint4*)(Ahi + baseA + kt * 64);
            uint4 l0 = *(const uint4*)(Alo + baseA + kt * 64);
            float x0[8];
            const __half2* hp0 = (const __half2*)&h0;
            const __half2* lp0 = (const __half2*)&l0;
            #pragma unroll
            for (int q = 0; q < 4; ++q) {
                float2 a = __half22float2(hp0[q]), b = __half22float2(lp0[q]);
                x0[2*q] = a.x + b.x; x0[2*q+1] = a.y + b.y;
            }
            #pragma unroll
            for (int kk = 0; kk < 8; ++kk) {
                int k = kt * 8 + kk;
                ULL a0 = f2dup(x0[kk]);
                #pragma unroll
                for (int j = 0; j < 3; ++j)
                    a3[j] = ffma2(a0, W3s64[k * 12 + 3 * gq + j], a3[j]);
            }
        }
        #pragma unroll
        for (int j = 0; j < 3; ++j) {
            float2 bb = ((const float2*)b3)[3 * gq + j];
            float2 v0 = f2unpack(a3[j]);
            logit_s[rp * 25 + 6 * gq + 2 * j]     = v0.x + bb.x;
            logit_s[rp * 25 + 6 * gq + 2 * j + 1] = v0.y + bb.y;
        }
    }
    __syncthreads();

    // ---- top-6 of 22 selected + borderline flagging (per-CTA) + write ----
    if (tid < 64) {
        const float* logit_s = (const float*)(smc + OFF_LG);
        const int row = bm0 + tid;
        float v[24];
        #pragma unroll
        for (int c = 0; c < 24; ++c) v[c] = logit_s[tid * 25 + c];

        unsigned chosen = 1u | (1u << 12);
        float lastBest = 0.0f;
        #pragma unroll
        for (int it = 0; it < 6; ++it) {
            float best = -3.402823466e38f;
            int bi = 1;
            #pragma unroll
            for (int c = 1; c < 24; ++c) {
                if (c == 12) continue;
                bool free_ = !((chosen >> c) & 1u);
                if (free_ && v[c] > best) { best = v[c]; bi = c; }  // strict >: lower index wins ties
            }
            chosen |= (1u << bi);
            lastBest = best;
        }
        float v7 = -3.402823466e38f;
        #pragma unroll
        for (int c = 1; c < 24; ++c) {
            if (c == 12) continue;
            if (!((chosen >> c) & 1u)) v7 = fmaxf(v7, v[c]);
        }
        if (lastBest - v7 < TAU) {
            int idx = atomicAdd(&s_cnt, 1);
            s_list[idx] = (unsigned char)tid;
        }

        float o[24];
        #pragma unroll
        for (int c = 0; c < 24; ++c) o[c] = ((chosen >> c) & 1u) ? 1.0f : 0.0f;
        float4* op = (float4*)(out + (size_t)row * 24);
        #pragma unroll
        for (int g2 = 0; g2 < 6; ++g2)
            op[g2] = make_float4(o[4 * g2], o[4 * g2 + 1], o[4 * g2 + 2], o[4 * g2 + 3]);
    }
    __syncthreads();

    // ---- inline exact fp32 fixup for this CTA's flagged rows ----
    const int fcnt = s_cnt;
    if (fcnt > 0) {
        float* xa  = (float*)smc;
        float* xb  = xa + 256;
        float* lg2 = xb + 256;
        const int j = tid;
        #pragma unroll 1
        for (int i = 0; i < fcnt; ++i) {
            const int row = bm0 + (int)s_list[i];
            xa[j] = X[(size_t)row * 256 + j];
            __syncthreads();
            {
                float s = 0.0f;
                #pragma unroll 32
                for (int k = 0; k < 256; ++k) s = fmaf(xa[k], W1f[(size_t)k * 256 + j], s);
                xb[j] = fmaxf(s + b1[j], 0.0f);
            }
            __syncthreads();
            {
                float s = 0.0f;
                #pragma unroll 32
                for (int k = 0; k < 256; ++k) s = fmaf(xb[k], W2f[(size_t)k * 256 + j], s);
                xa[j] = fmaxf(s + b2[j], 0.0f);
            }
            __syncthreads();
            if (j < 24) {
                float s = 0.0f;
                #pragma unroll 32
                for (int k = 0; k < 256; ++k) s = fmaf(xa[k], W3[(size_t)k * 24 + j], s);
                lg2[j] = s + b3[j];
            }
            __syncthreads();
            if (j == 0) {
                float v[24];
                #pragma unroll
                for (int c = 0; c < 24; ++c) v[c] = lg2[c];
                unsigned chosen = 1u | (1u << 12);
                #pragma unroll
                for (int it = 0; it < 6; ++it) {
                    float best = -3.402823466e38f;
                    int bi = 1;
                    #pragma unroll
                    for (int c = 1; c < 24; ++c) {
                        if (c == 12) continue;
                        bool free_ = !((chosen >> c) & 1u);
                        if (free_ && v[c] > best) { best = v[c]; bi = c; }
                    }
                    chosen |= (1u << bi);
                }
                float* op = out + (size_t)row * 24;
                #pragma unroll
                for (int c = 0; c < 24; ++c) op[c] = ((chosen >> c) & 1u) ? 1.0f : 0.0f;
            }
            __syncthreads();
        }
    }
}

extern "C" void kernel_launch(void* const* d_in, const int* in_sizes, int n_in,
                              void* d_out, int out_size) {
    const float* X  = (const float*)d_in[0];
    const float* W1 = (const float*)d_in[1];
    const float* b1 = (const float*)d_in[2];
    const float* W2 = (const float*)d_in[3];
    const float* b2 = (const float*)d_in[4];
    const float* W3 = (const float*)d_in[5];
    const float* b3 = (const float*)d_in[6];
    float* out = (float*)d_out;

    int B = in_sizes[0] / 256;

    prep_kernel<<<256, 256>>>(W1, W2);

    cudaFuncSetAttribute(fused_mlp_hmma, cudaFuncAttributeMaxDynamicSharedMemorySize, SMEM_BYTES);
    fused_mlp_hmma<<<B / 64, 256, SMEM_BYTES>>>(X, W1, b1, W2, b2, W3, b3, out);
}